// round 1
// baseline (speedup 1.0000x reference)
#include <cuda_runtime.h>
#include <math.h>

// ---------------- problem constants ----------------
// text : [2,64,256]  -> tf   [L=128, N=256]
// image: [2,64,32,64,64] -> imf [L=128, M=131072]
// cost[n,m] = ||a_n - b_m||,  a_n = tf[:,n], b_m = imf[:,m]
// Sinkhorn collapses: u = v = 0.01 exactly (see analysis) ->
//   T[n,m] = 1e-4 * exp(-0.1*cost[n,m])
// aligned[l,n] = sum_m imf[l,m] * T[n,m]
// t_line[b,c,w] = 0.5*(aligned[l,4w+1] + aligned[l,4w+2]),  l = b*64+c
// per-voxel MLP: h = relu(W1a@t_line + W1b@x + b1); g = sigmoid(W2@h + b2)
// out = x*(1-g) + t_line*g

#define L_DIM   128
#define N_DIM   256
#define M_DIM   131072
#define C_DIM   64
#define IMG_BSTRIDE 8388608   // 64*131072

// ---------------- scratch (static device memory; no allocs) ----------------
__device__ float g_E[(size_t)M_DIM * N_DIM];      // E[m][n], 134 MB
__device__ float g_part[256 * 8192];              // split-K partials, 8 MB
__device__ float g_bn2[M_DIM];
__device__ float g_an2[N_DIM];
__device__ float g_al[L_DIM * N_DIM];             // aligned [l][n]
__device__ float g_tline[2 * 64 * 64];            // [b][c][w]
__device__ float g_pre1[2 * 64 * 64];             // [b][o][w] : b1 + W1a@t_line

// ================= K0: squared norms =================
__global__ void k_norms(const float* __restrict__ img, const float* __restrict__ text) {
    int bid = blockIdx.x, t = threadIdx.x;
    if (bid < 512) {
        int m = bid * 256 + t;
        float s = 0.f;
        #pragma unroll 8
        for (int l = 0; l < L_DIM; l++) {
            float v = img[(size_t)l * M_DIM + m];
            s = fmaf(v, v, s);
        }
        g_bn2[m] = s;
    } else {
        int n = t;
        float s = 0.f;
        #pragma unroll 8
        for (int l = 0; l < L_DIM; l++) {
            float v = text[l * N_DIM + n];
            s = fmaf(v, v, s);
        }
        g_an2[n] = s;
    }
}

// ================= K1: E[m][n] = 1e-4 * exp(-0.1*cost) =================
// Block: 256 threads, tile = all 256 n x 64 m. micro: 8n(spread) x 8m.
// thread: tn = t&31 -> n = tn + 32*i ; warp id tw = t>>5 -> m = m0 + 8*tw + j.
__global__ __launch_bounds__(256) void k_expcost(const float* __restrict__ img,
                                                 const float* __restrict__ text) {
    __shared__ float As[32 * 256];   // [lc][n]
    __shared__ float Bs[32 * 64];    // [lc][mm]
    __shared__ float an2s[256];
    __shared__ float bn2s[64];

    int t = threadIdx.x;
    int m0 = blockIdx.x * 64;
    int tn = t & 31;
    int tw = t >> 5;

    an2s[t] = g_an2[t];
    if (t < 64) bn2s[t] = g_bn2[m0 + t];

    float acc[8][8];
    #pragma unroll
    for (int i = 0; i < 8; i++)
        #pragma unroll
        for (int j = 0; j < 8; j++) acc[i][j] = 0.f;

    for (int l0 = 0; l0 < L_DIM; l0 += 32) {
        __syncthreads();
        #pragma unroll
        for (int r = 0; r < 32; r++)
            As[t + 256 * r] = text[(l0 + r) * N_DIM + t];
        #pragma unroll
        for (int r = 0; r < 8; r++) {
            int f = t + 256 * r;
            Bs[f] = img[(size_t)(l0 + (f >> 6)) * M_DIM + m0 + (f & 63)];
        }
        __syncthreads();

        #pragma unroll 4
        for (int lc = 0; lc < 32; lc++) {
            float a[8], b[8];
            #pragma unroll
            for (int i = 0; i < 8; i++) a[i] = As[lc * 256 + tn + 32 * i];
            #pragma unroll
            for (int j = 0; j < 8; j++) b[j] = Bs[lc * 64 + tw * 8 + j];
            #pragma unroll
            for (int i = 0; i < 8; i++)
                #pragma unroll
                for (int j = 0; j < 8; j++)
                    acc[i][j] = fmaf(a[i], b[j], acc[i][j]);
        }
    }

    // epilogue: write E[m][n], coalesced across lanes (n = tn + 32*i consecutive)
    #pragma unroll
    for (int j = 0; j < 8; j++) {
        int m = m0 + tw * 8 + j;
        float bn = bn2s[tw * 8 + j];
        #pragma unroll
        for (int i = 0; i < 8; i++) {
            int n = tn + 32 * i;
            float d2 = an2s[n] + bn - 2.f * acc[i][j];
            float cst = sqrtf(fmaxf(d2, 0.f));
            g_E[(size_t)m * N_DIM + n] = 1e-4f * expf(-0.1f * cst);
        }
    }
}

// ================= K2: split-K partials of aligned[l][n] = sum_m imf[l,m]*E[m,n] ==========
// grid 256: nt = blockIdx&3 (n-tile of 64), s = blockIdx>>2 (m-stripe of 2048)
// block tile: 128 l x 64 n; thread micro 4l x 8n.
__global__ __launch_bounds__(256) void k_gemm2(const float* __restrict__ img) {
    __shared__ float Is[128 * 33];  // [l][mc], padded
    __shared__ float Es[32 * 64];   // [mc][nn]

    int t = threadIdx.x;
    int nt = blockIdx.x & 3;
    int s  = blockIdx.x >> 2;
    int n0 = nt * 64;
    int mstart = s * 2048;
    int tl = t >> 3;   // 0..31
    int tn = t & 7;    // 0..7

    float acc[4][8];
    #pragma unroll
    for (int a = 0; a < 4; a++)
        #pragma unroll
        for (int b = 0; b < 8; b++) acc[a][b] = 0.f;

    for (int mc0 = 0; mc0 < 2048; mc0 += 32) {
        int mbase = mstart + mc0;
        __syncthreads();
        #pragma unroll
        for (int r = 0; r < 16; r++) {
            int f = t + 256 * r;
            Is[(f >> 5) * 33 + (f & 31)] =
                img[(size_t)(f >> 5) * M_DIM + mbase + (f & 31)];
        }
        #pragma unroll
        for (int r = 0; r < 8; r++) {
            int f = t + 256 * r;
            Es[f] = g_E[(size_t)(mbase + (f >> 6)) * N_DIM + n0 + (f & 63)];
        }
        __syncthreads();

        #pragma unroll 4
        for (int mc = 0; mc < 32; mc++) {
            float a[4], e[8];
            #pragma unroll
            for (int ll = 0; ll < 4; ll++) a[ll] = Is[(4 * tl + ll) * 33 + mc];
            #pragma unroll
            for (int i = 0; i < 8; i++) e[i] = Es[mc * 64 + tn + 8 * i];
            #pragma unroll
            for (int ll = 0; ll < 4; ll++)
                #pragma unroll
                for (int i = 0; i < 8; i++)
                    acc[ll][i] = fmaf(a[ll], e[i], acc[ll][i]);
        }
    }

    float* p = g_part + (size_t)blockIdx.x * 8192;
    #pragma unroll
    for (int ll = 0; ll < 4; ll++)
        #pragma unroll
        for (int i = 0; i < 8; i++)
            p[(4 * tl + ll) * 64 + tn + 8 * i] = acc[ll][i];
}

// ================= K2b: deterministic reduction of partials =================
__global__ void k_reduce() {
    int id = blockIdx.x * 256 + threadIdx.x;   // 0..32767
    int l = id >> 8, n = id & 255;
    int nt = n >> 6, nn = n & 63;
    float s = 0.f;
    #pragma unroll 8
    for (int st = 0; st < 64; st++)
        s += g_part[(size_t)(st * 4 + nt) * 8192 + l * 64 + nn];
    g_al[l * 256 + n] = s;
}

// ================= K2c: t_line + pre1 =================
__global__ void k_prep(const float* __restrict__ w1, const float* __restrict__ b1) {
    __shared__ float tls[8192];   // [l][w]
    int t = threadIdx.x;
    for (int f = t; f < 8192; f += 256) {
        int l = f >> 6, w = f & 63;
        float v = 0.5f * (g_al[l * 256 + 4 * w + 1] + g_al[l * 256 + 4 * w + 2]);
        tls[f] = v;
        g_tline[f] = v;
    }
    __syncthreads();
    for (int f = t; f < 8192; f += 256) {
        int b = f >> 12, o = (f >> 6) & 63, w = f & 63;
        float s = b1[o];
        #pragma unroll 8
        for (int c = 0; c < 64; c++)
            s = fmaf(w1[o * 128 + c], tls[(b * 64 + c) * 64 + w], s);
        g_pre1[f] = s;   // layout [b][o][w]
    }
}

// ================= K3: per-voxel MLP + gated blend =================
// 64 threads/block, 64 voxels/block (one w-row). 48KB static smem.
__global__ __launch_bounds__(64) void k_mlp(const float* __restrict__ img,
                                            const float* __restrict__ w1,
                                            const float* __restrict__ w2,
                                            const float* __restrict__ b2,
                                            float* __restrict__ out) {
    __shared__ float Hs[4096];   // [o][vox]
    __shared__ float w1s[4096];  // [o][c]  (image half of w1)
    __shared__ float w2s[4096];  // [o][c]

    int t = threadIdx.x;                 // 0..63, also w index (m0 % 64 == 0)
    int bb = blockIdx.x >> 11;           // batch
    int m0 = (blockIdx.x & 2047) * 64;

    for (int f = t; f < 4096; f += 64) {
        w1s[f] = w1[(f >> 6) * 128 + 64 + (f & 63)];
        w2s[f] = w2[f];
    }
    __syncthreads();

    const float* ib = img + (size_t)bb * IMG_BSTRIDE + m0 + t;
    const float* pr = g_pre1 + bb * 4096;   // [o][w]
    const float* tl = g_tline + bb * 4096;  // [c][w]

    float h[64];
    #pragma unroll
    for (int o = 0; o < 64; o++) h[o] = pr[o * 64 + t];

    for (int c = 0; c < 64; c++) {
        float xv = ib[(size_t)c * M_DIM];
        #pragma unroll
        for (int o = 0; o < 64; o++)
            h[o] = fmaf(w1s[o * 64 + c], xv, h[o]);
    }
    #pragma unroll
    for (int o = 0; o < 64; o++) Hs[o * 64 + t] = fmaxf(h[o], 0.f);

    float g[64];
    #pragma unroll
    for (int o = 0; o < 64; o++) g[o] = b2[o];

    for (int c = 0; c < 64; c++) {
        float hv = Hs[c * 64 + t];
        #pragma unroll
        for (int o = 0; o < 64; o++)
            g[o] = fmaf(w2s[o * 64 + c], hv, g[o]);
    }

    float* ob = out + (size_t)bb * IMG_BSTRIDE + m0 + t;
    #pragma unroll
    for (int o = 0; o < 64; o++) {
        float gate = 1.f / (1.f + expf(-g[o]));
        float xv = ib[(size_t)o * M_DIM];
        ob[(size_t)o * M_DIM] = xv + (tl[o * 64 + t] - xv) * gate;
    }
}

// ================= launch =================
extern "C" void kernel_launch(void* const* d_in, const int* in_sizes, int n_in,
                              void* d_out, int out_size) {
    const float* text = (const float*)d_in[0];
    const float* img  = (const float*)d_in[1];
    const float* w1   = (const float*)d_in[2];
    const float* b1   = (const float*)d_in[3];
    const float* w2   = (const float*)d_in[4];
    const float* b2   = (const float*)d_in[5];
    float* out = (float*)d_out;

    k_norms  <<<513, 256>>>(img, text);
    k_expcost<<<2048, 256>>>(img, text);
    k_gemm2  <<<256, 256>>>(img);
    k_reduce <<<128, 256>>>();
    k_prep   <<<1, 256>>>(w1, b1);
    k_mlp    <<<4096, 64>>>(img, w1, w2, b2, out);
}

// round 2
// speedup vs baseline: 1.2415x; 1.2415x over previous
#include <cuda_runtime.h>
#include <math.h>

// ---------------- problem constants ----------------
#define L_DIM   128
#define N_DIM   256
#define M_DIM   131072
#define IMG_BSTRIDE 8388608   // 64*131072

// ---------------- scratch (static device memory; no allocs) ----------------
__device__ float g_E[(size_t)M_DIM * N_DIM];      // E[m][n], 134 MB
__device__ float g_part[256 * 16384];             // split-K partials, 16.8 MB
__device__ float g_bn2[M_DIM];
__device__ float g_an2[N_DIM];
__device__ float g_al[L_DIM * N_DIM];             // aligned [l][n]
__device__ float g_tline[2 * 64 * 64];            // [b][c][w]
__device__ float g_pre1[2 * 64 * 64];             // [b][o][w] : b1 + W1a@t_line

// ---------------- fast math (FMA pipe only, no MUFU) ----------------
__device__ __forceinline__ float fast_rsqrt(float x) {
    float r = __int_as_float(0x5f3759df - (__float_as_int(x) >> 1));
    r = r * fmaf(-0.5f * x, r * r, 1.5f);
    r = r * fmaf(-0.5f * x, r * r, 1.5f);
    return r;
}

// 2^x for x in ~[-120, 0]; rel err ~1.3e-6
__device__ __forceinline__ float fast_exp2(float x) {
    float fl = floorf(x);
    float f = x - fl;                       // [0,1)
    float p = 1.5252733804059841e-05f;
    p = fmaf(p, f, 1.5403530393381609e-04f);
    p = fmaf(p, f, 1.3333558146428443e-03f);
    p = fmaf(p, f, 9.6181291076284772e-03f);
    p = fmaf(p, f, 5.5504108664821580e-02f);
    p = fmaf(p, f, 2.4022650695910072e-01f);
    p = fmaf(p, f, 6.9314718055994531e-01f);
    p = fmaf(p, f, 1.0f);
    return __int_as_float(__float_as_int(p) + ((int)fl << 23));
}

__device__ __forceinline__ float fast_sigmoid(float x) {
    float ax = fminf(fabsf(x) * 1.4426950408889634f, 120.0f);
    float p = fast_exp2(-ax);               // (0,1]
    float d = 1.0f + p;                     // (1,2]
    float r = __int_as_float(0x7EF311C3 - __float_as_int(d));
    r = r * fmaf(-d, r, 2.0f);
    r = r * fmaf(-d, r, 2.0f);
    r = r * fmaf(-d, r, 2.0f);
    float num = (x >= 0.0f) ? 1.0f : p;
    return num * r;
}

// ================= K0: squared norms =================
__global__ void k_norms(const float* __restrict__ img, const float* __restrict__ text) {
    int bid = blockIdx.x, t = threadIdx.x;
    if (bid < 512) {
        int m = bid * 256 + t;
        float s = 0.f;
        #pragma unroll 8
        for (int l = 0; l < L_DIM; l++) {
            float v = img[(size_t)l * M_DIM + m];
            s = fmaf(v, v, s);
        }
        g_bn2[m] = s;
    } else {
        int n = t;
        float s = 0.f;
        #pragma unroll 8
        for (int l = 0; l < L_DIM; l++) {
            float v = text[l * N_DIM + n];
            s = fmaf(v, v, s);
        }
        g_an2[n] = s;
    }
}

// ================= K1: E[m][n] = 1e-4 * exp(-0.1*cost) =================
__global__ __launch_bounds__(256) void k_expcost(const float* __restrict__ img,
                                                 const float* __restrict__ text) {
    __shared__ float As[32 * 256];   // [lc][n]
    __shared__ float Bs[32 * 64];    // [lc][mm]
    __shared__ float an2s[256];
    __shared__ float bn2s[64];

    int t = threadIdx.x;
    int m0 = blockIdx.x * 64;
    int tn = t & 31;
    int tw = t >> 5;

    an2s[t] = g_an2[t];
    if (t < 64) bn2s[t] = g_bn2[m0 + t];

    float acc[8][8];
    #pragma unroll
    for (int i = 0; i < 8; i++)
        #pragma unroll
        for (int j = 0; j < 8; j++) acc[i][j] = 0.f;

    for (int l0 = 0; l0 < L_DIM; l0 += 32) {
        __syncthreads();
        #pragma unroll
        for (int r = 0; r < 32; r++)
            As[t + 256 * r] = text[(l0 + r) * N_DIM + t];
        #pragma unroll
        for (int r = 0; r < 8; r++) {
            int f = t + 256 * r;
            Bs[f] = img[(size_t)(l0 + (f >> 6)) * M_DIM + m0 + (f & 63)];
        }
        __syncthreads();

        #pragma unroll 4
        for (int lc = 0; lc < 32; lc++) {
            float a[8], b[8];
            #pragma unroll
            for (int i = 0; i < 8; i++) a[i] = As[lc * 256 + tn + 32 * i];
            #pragma unroll
            for (int j = 0; j < 8; j++) b[j] = Bs[lc * 64 + tw * 8 + j];
            #pragma unroll
            for (int i = 0; i < 8; i++)
                #pragma unroll
                for (int j = 0; j < 8; j++)
                    acc[i][j] = fmaf(a[i], b[j], acc[i][j]);
        }
    }

    // epilogue: cost = sqrt(d2) via rsqrt-Newton; E = 1e-4 * 2^(-0.144269*cost)
    #pragma unroll
    for (int j = 0; j < 8; j++) {
        int m = m0 + tw * 8 + j;
        float bn = bn2s[tw * 8 + j];
        #pragma unroll
        for (int i = 0; i < 8; i++) {
            int n = tn + 32 * i;
            float d2 = fmaxf(an2s[n] + bn - 2.f * acc[i][j], 0.f);
            float cst = d2 * fast_rsqrt(d2);           // sqrt(d2); 0 -> 0
            g_E[(size_t)m * N_DIM + n] =
                1e-4f * fast_exp2(-0.14426950408889634f * cst);
        }
    }
}

// ================= K2: split-K partials of aligned[l][n] =================
// grid 256: nt = blockIdx&1 (n-tile of 128), s = blockIdx>>1 (m-stripe of 1024)
// block tile: 128 l x 128 n; thread micro 8l x 8n (FMA-bound: 1 B/FMA)
__global__ __launch_bounds__(256) void k_gemm2(const float* __restrict__ img) {
    __shared__ float Is[128 * 33];   // [l][mc], padded
    __shared__ float Es[32 * 128];   // [mc][nn]

    int t = threadIdx.x;
    int nt = blockIdx.x & 1;
    int s  = blockIdx.x >> 1;        // 0..127
    int n0 = nt * 128;
    int mstart = s * 1024;
    int tx = t & 15;                 // n = tx*8 + i
    int ty = t >> 4;                 // l = ty*8 + j

    float acc[8][8];
    #pragma unroll
    for (int j = 0; j < 8; j++)
        #pragma unroll
        for (int i = 0; i < 8; i++) acc[j][i] = 0.f;

    for (int mc0 = 0; mc0 < 1024; mc0 += 32) {
        int mbase = mstart + mc0;
        __syncthreads();
        #pragma unroll
        for (int r = 0; r < 16; r++) {
            int f = t + 256 * r;
            Is[(f >> 5) * 33 + (f & 31)] =
                img[(size_t)(f >> 5) * M_DIM + mbase + (f & 31)];
        }
        #pragma unroll
        for (int r = 0; r < 16; r++) {
            int f = t + 256 * r;
            Es[f] = g_E[(size_t)(mbase + (f >> 7)) * N_DIM + n0 + (f & 127)];
        }
        __syncthreads();

        #pragma unroll 4
        for (int mc = 0; mc < 32; mc++) {
            float a[8], e[8];
            #pragma unroll
            for (int j = 0; j < 8; j++) a[j] = Is[(ty * 8 + j) * 33 + mc];
            float4 e0 = *(const float4*)&Es[mc * 128 + tx * 8];
            float4 e1 = *(const float4*)&Es[mc * 128 + tx * 8 + 4];
            e[0] = e0.x; e[1] = e0.y; e[2] = e0.z; e[3] = e0.w;
            e[4] = e1.x; e[5] = e1.y; e[6] = e1.z; e[7] = e1.w;
            #pragma unroll
            for (int j = 0; j < 8; j++)
                #pragma unroll
                for (int i = 0; i < 8; i++)
                    acc[j][i] = fmaf(a[j], e[i], acc[j][i]);
        }
    }

    float* p = g_part + (size_t)blockIdx.x * 16384;
    #pragma unroll
    for (int j = 0; j < 8; j++) {
        #pragma unroll
        for (int i = 0; i < 8; i += 4) {
            float4 v = make_float4(acc[j][i], acc[j][i + 1], acc[j][i + 2], acc[j][i + 3]);
            *(float4*)&p[(ty * 8 + j) * 128 + tx * 8 + i] = v;
        }
    }
}

// ================= K2b: deterministic reduction of partials =================
__global__ void k_reduce() {
    int id = blockIdx.x * 256 + threadIdx.x;   // 0..32767
    int l = id >> 8, n = id & 255;
    int nt = n >> 7, nn = n & 127;
    float s = 0.f;
    #pragma unroll 8
    for (int st = 0; st < 128; st++)
        s += g_part[(size_t)(st * 2 + nt) * 16384 + l * 128 + nn];
    g_al[l * 256 + n] = s;
}

// ================= K2c: t_line + pre1 =================
__global__ void k_prep(const float* __restrict__ w1, const float* __restrict__ b1) {
    __shared__ float tls[8192];   // [l][w]
    int t = threadIdx.x;
    for (int f = t; f < 8192; f += 256) {
        int l = f >> 6, w = f & 63;
        float v = 0.5f * (g_al[l * 256 + 4 * w + 1] + g_al[l * 256 + 4 * w + 2]);
        tls[f] = v;
        g_tline[f] = v;
    }
    __syncthreads();
    for (int f = t; f < 8192; f += 256) {
        int b = f >> 12, o = (f >> 6) & 63, w = f & 63;
        float s = b1[o];
        #pragma unroll 8
        for (int c = 0; c < 64; c++)
            s = fmaf(w1[o * 128 + c], tls[(b * 64 + c) * 64 + w], s);
        g_pre1[f] = s;   // layout [b][o][w]
    }
}

// ================= K3: per-voxel MLP + gated blend =================
// 128 threads/block, 128 voxels/block. smem = 48KB exactly:
//   sw2[4096]  : w2 transposed [c][o]
//   sbuf[8192] : w1 transposed [c][o] (first 4096) during GEMM1, then H [c][vox]
__global__ __launch_bounds__(128) void k_mlp(const float* __restrict__ img,
                                             const float* __restrict__ w1,
                                             const float* __restrict__ w2,
                                             const float* __restrict__ b2,
                                             float* __restrict__ out) {
    __shared__ float sw2[4096];
    __shared__ float sbuf[8192];

    int t = threadIdx.x;
    int bb = blockIdx.x >> 10;
    int m0 = (blockIdx.x & 1023) << 7;
    int w = t & 63;

    // load weights transposed [c][o]; stores are conflict-free (o varies per lane)
    for (int f = t; f < 4096; f += 128) {
        int o = f & 63, c = f >> 6;
        sbuf[c * 64 + o] = w1[o * 128 + 64 + c];   // image half of w1
        sw2[c * 64 + o] = w2[o * 64 + c];
    }
    __syncthreads();

    const float* ib = img + (size_t)bb * IMG_BSTRIDE + m0 + t;
    const float* pr = g_pre1 + bb * 4096;

    float h[64];
    #pragma unroll
    for (int o = 0; o < 64; o++) h[o] = pr[o * 64 + w];

    // GEMM1: h[o] += w1[o][64+c] * x[c]; weights read as uniform float4 broadcasts
    #pragma unroll 2
    for (int c = 0; c < 64; c++) {
        float xv = ib[(size_t)c * M_DIM];
        const float4* wr = (const float4*)&sbuf[c * 64];
        #pragma unroll
        for (int q = 0; q < 16; q++) {
            float4 wv = wr[q];
            h[4 * q + 0] = fmaf(wv.x, xv, h[4 * q + 0]);
            h[4 * q + 1] = fmaf(wv.y, xv, h[4 * q + 1]);
            h[4 * q + 2] = fmaf(wv.z, xv, h[4 * q + 2]);
            h[4 * q + 3] = fmaf(wv.w, xv, h[4 * q + 3]);
        }
    }
    __syncthreads();   // everyone done reading w1 half of sbuf

    // H -> smem [c][vox]
    #pragma unroll
    for (int o = 0; o < 64; o++) sbuf[o * 128 + t] = fmaxf(h[o], 0.f);
    __syncthreads();

    // GEMM2: g[o] = b2[o] + sum_c w2[o][c] * H[c]
    float g[64];
    #pragma unroll
    for (int o = 0; o < 64; o++) g[o] = __ldg(&b2[o]);

    #pragma unroll 2
    for (int c = 0; c < 64; c++) {
        float hv = sbuf[c * 128 + t];
        const float4* wr = (const float4*)&sw2[c * 64];
        #pragma unroll
        for (int q = 0; q < 16; q++) {
            float4 wv = wr[q];
            g[4 * q + 0] = fmaf(wv.x, hv, g[4 * q + 0]);
            g[4 * q + 1] = fmaf(wv.y, hv, g[4 * q + 1]);
            g[4 * q + 2] = fmaf(wv.z, hv, g[4 * q + 2]);
            g[4 * q + 3] = fmaf(wv.w, hv, g[4 * q + 3]);
        }
    }

    // epilogue: out = x + (t_line - x) * sigmoid(g)
    float* ob = out + (size_t)bb * IMG_BSTRIDE + m0 + t;
    const float* tl = g_tline + bb * 4096;
    #pragma unroll
    for (int o = 0; o < 64; o++) {
        float gate = fast_sigmoid(g[o]);
        float xv = ib[(size_t)o * M_DIM];
        float tv = tl[o * 64 + w];
        ob[(size_t)o * M_DIM] = fmaf(gate, tv - xv, xv);
    }
}

// ================= launch =================
extern "C" void kernel_launch(void* const* d_in, const int* in_sizes, int n_in,
                              void* d_out, int out_size) {
    const float* text = (const float*)d_in[0];
    const float* img  = (const float*)d_in[1];
    const float* w1   = (const float*)d_in[2];
    const float* b1   = (const float*)d_in[3];
    const float* w2   = (const float*)d_in[4];
    const float* b2   = (const float*)d_in[5];
    float* out = (float*)d_out;

    k_norms  <<<513, 256>>>(img, text);
    k_expcost<<<2048, 256>>>(img, text);
    k_gemm2  <<<256, 256>>>(img);
    k_reduce <<<128, 256>>>();
    k_prep   <<<1, 256>>>(w1, b1);
    k_mlp    <<<2048, 128>>>(img, w1, w2, b2, out);
}

// round 4
// speedup vs baseline: 2.1538x; 1.7348x over previous
#include <cuda_runtime.h>
#include <cuda_bf16.h>
#include <math.h>
#include <stdint.h>

// ---------------- problem constants ----------------
#define L_DIM   128
#define N_DIM   256
#define M_DIM   131072
#define IMG_BSTRIDE 8388608   // 64*131072

// ---------------- scratch (static device memory; no allocs) ----------------
__device__ __align__(16) unsigned g_text16u[256 * 64];        // bf16 [n][l] pairs
__device__ __align__(16) unsigned g_img16u[(size_t)M_DIM * 64]; // bf16 [m][l] pairs (33.5MB)
__device__ float g_part[128 * 32768];          // per-CTA alignedT partials [s][n][l] (16.8MB)
__device__ float g_bn2[M_DIM];
__device__ float g_an2[N_DIM];
__device__ float g_al[L_DIM * N_DIM];          // aligned [l][n]
__device__ float g_tline[2 * 64 * 64];         // [b][c][w]
__device__ float g_pre1[2 * 64 * 64];          // [b][o][w]

// ---------------- fast math (FMA pipe only) ----------------
__device__ __forceinline__ float fast_rsqrt(float x) {
    float r = __int_as_float(0x5f3759df - (__float_as_int(x) >> 1));
    r = r * fmaf(-0.5f * x, r * r, 1.5f);
    r = r * fmaf(-0.5f * x, r * r, 1.5f);
    return r;
}
__device__ __forceinline__ float fast_exp2(float x) {
    float fl = floorf(x);
    float f = x - fl;
    float p = 1.5252733804059841e-05f;
    p = fmaf(p, f, 1.5403530393381609e-04f);
    p = fmaf(p, f, 1.3333558146428443e-03f);
    p = fmaf(p, f, 9.6181291076284772e-03f);
    p = fmaf(p, f, 5.5504108664821580e-02f);
    p = fmaf(p, f, 2.4022650695910072e-01f);
    p = fmaf(p, f, 6.9314718055994531e-01f);
    p = fmaf(p, f, 1.0f);
    return __int_as_float(__float_as_int(p) + ((int)fl << 23));
}
__device__ __forceinline__ float fast_sigmoid(float x) {
    float ax = fminf(fabsf(x) * 1.4426950408889634f, 120.0f);
    float p = fast_exp2(-ax);
    float d = 1.0f + p;
    float r = __int_as_float(0x7EF311C3 - __float_as_int(d));
    r = r * fmaf(-d, r, 2.0f);
    r = r * fmaf(-d, r, 2.0f);
    r = r * fmaf(-d, r, 2.0f);
    float num = (x >= 0.0f) ? 1.0f : p;
    return num * r;
}
__device__ __forceinline__ float efun(float dot, float an, float bn) {
    float d2 = fmaxf(an + bn - 2.f * dot, 0.f);
    float cst = d2 * fast_rsqrt(fmaxf(d2, 1e-20f));
    return 1e-4f * fast_exp2(-0.14426950408889634f * cst);
}

// ---------------- warp MMA helpers (compute_80+, valid on compute_103) ----------------
__device__ __forceinline__ uint32_t smem_u32(const void* p) {
    uint32_t a;
    asm("{ .reg .u64 t; cvta.to.shared.u64 t, %1; cvt.u32.u64 %0, t; }" : "=r"(a) : "l"(p));
    return a;
}
__device__ __forceinline__ void ldsm4(uint32_t* r, uint32_t a) {
    asm volatile("ldmatrix.sync.aligned.m8n8.x4.shared.b16 {%0,%1,%2,%3}, [%4];"
                 : "=r"(r[0]), "=r"(r[1]), "=r"(r[2]), "=r"(r[3]) : "r"(a));
}
__device__ __forceinline__ void ldsm4t(uint32_t* r, uint32_t a) {
    asm volatile("ldmatrix.sync.aligned.m8n8.x4.trans.shared.b16 {%0,%1,%2,%3}, [%4];"
                 : "=r"(r[0]), "=r"(r[1]), "=r"(r[2]), "=r"(r[3]) : "r"(a));
}
__device__ __forceinline__ void mma_bf16(float* d, const uint32_t* a,
                                         uint32_t b0, uint32_t b1) {
    asm volatile("mma.sync.aligned.m16n8k16.row.col.f32.bf16.bf16.f32 "
                 "{%0,%1,%2,%3}, {%4,%5,%6,%7}, {%8,%9}, {%0,%1,%2,%3};"
                 : "+f"(d[0]), "+f"(d[1]), "+f"(d[2]), "+f"(d[3])
                 : "r"(a[0]), "r"(a[1]), "r"(a[2]), "r"(a[3]), "r"(b0), "r"(b1));
}
__device__ __forceinline__ uint32_t pack_bf16(float lo, float hi) {
    uint32_t r;
    asm("cvt.rn.bf16x2.f32 %0, %1, %2;" : "=r"(r) : "f"(hi), "f"(lo));
    return r;
}

// ================= K0: prepass — bf16 row-major tiles + norms =================
// blocks 0..1023: img m-chunk of 128 -> g_img16u [m][l], g_bn2.
// block 1024: text -> g_text16u [n][l], g_an2.
__global__ __launch_bounds__(256) void k_prepass(const float* __restrict__ img,
                                                 const float* __restrict__ text) {
    extern __shared__ float smemf[];   // 128 x 129 floats
    int b = blockIdx.x, t = threadIdx.x;

    if (b < 1024) {
        int m0 = b << 7;
        for (int f = t; f < 16384; f += 256)
            smemf[(f >> 7) * 129 + (f & 127)] =
                img[(size_t)(f >> 7) * M_DIM + m0 + (f & 127)];   // smem [l][m]
        __syncthreads();
        if (t < 128) {
            float s = 0.f;
            #pragma unroll 8
            for (int l = 0; l < 128; l++) {
                float v = smemf[l * 129 + t];
                s = fmaf(v, v, s);
            }
            g_bn2[m0 + t] = s;
        }
        for (int p = t; p < 8192; p += 256) {
            int row = p >> 6, c2 = p & 63;       // m-row, l-pair
            float a0 = smemf[(2 * c2) * 129 + row];
            float a1 = smemf[(2 * c2 + 1) * 129 + row];
            g_img16u[(size_t)(m0 + row) * 64 + c2] = pack_bf16(a0, a1);
        }
    } else {
        for (int p = t; p < 16384; p += 256) {
            int n = p >> 6, c2 = p & 63;
            float v0 = text[(2 * c2) * 256 + n];
            float v1 = text[(2 * c2 + 1) * 256 + n];
            g_text16u[n * 64 + c2] = pack_bf16(v0, v1);
        }
        float s = 0.f;
        #pragma unroll 8
        for (int l = 0; l < 128; l++) {
            float v = text[l * 256 + t];
            s = fmaf(v, v, s);
        }
        g_an2[t] = s;
    }
}

// ================= K1: fused tensor-core pipeline (mma.sync) =================
// 128 CTAs x 256 thr. Per CTA: m-stripe of 1024 (8 chunks of 128 m).
// Per chunk: GEMM1 D[n,m] = text.imgT (frag in regs) -> E epilogue in regs ->
// fragment-reuse as A of GEMM2: alignedT[n,l] += E[n,m].img[m,l].
// smem layout (bytes): stext bf16[256][136] @0 (69632) | simg bf16[128][136]
// @69632 (34816) | bn2s f32[1024] @104448 | an2s f32[256] @108544 | tot 109568
__global__ __launch_bounds__(256, 1) void k_fused() {
    extern __shared__ char dsm[];
    const int SIMG = 69632, BN2 = 104448, AN2 = 108544;
    float* bn2s = (float*)(dsm + BN2);
    float* an2s = (float*)(dsm + AN2);

    int t = threadIdx.x, bid = blockIdx.x;
    int w = t >> 5, lane = t & 31;
    uint32_t sb = smem_u32(dsm);
    uint32_t sbi = sb + SIMG;

    // persistent loads
    {
        uint4* stq = (uint4*)dsm;
        const uint4* tq = (const uint4*)g_text16u;
        for (int f = t; f < 4096; f += 256)
            stq[(f >> 4) * 17 + (f & 15)] = tq[f];
        #pragma unroll
        for (int i = 0; i < 4; i++) bn2s[t + 256 * i] = g_bn2[bid * 1024 + t + 256 * i];
        an2s[t] = g_an2[t];
    }

    float acc2[2][16][4];
    #pragma unroll
    for (int i = 0; i < 2; i++)
        #pragma unroll
        for (int lt = 0; lt < 16; lt++)
            #pragma unroll
            for (int r = 0; r < 4; r++) acc2[i][lt][r] = 0.f;

    __syncthreads();
    float an2v[2][2];
    #pragma unroll
    for (int i = 0; i < 2; i++) {
        an2v[i][0] = an2s[w * 32 + i * 16 + (lane >> 2)];
        an2v[i][1] = an2s[w * 32 + i * 16 + (lane >> 2) + 8];
    }

    // ldmatrix address lanes
    uint32_t a_row = (uint32_t)(w * 32 + (lane & 15));   // + i*16
    uint32_t a_colb = (uint32_t)((lane >> 4) * 16);      // + kk*32 bytes
    uint32_t b_rowb = (uint32_t)((lane & 15)) * 272u;    // + s*16*272
    uint32_t b_colb = (uint32_t)((lane >> 4) * 16);

    #pragma unroll 1
    for (int c = 0; c < 8; c++) {
        // load img chunk [128 m][128 l] bf16, padded stride 136
        {
            uint4* siq = (uint4*)(dsm + SIMG);
            const uint4* gq = (const uint4*)g_img16u + (size_t)(bid * 8 + c) * 2048;
            for (int f = t; f < 2048; f += 256)
                siq[(f >> 4) * 17 + (f & 15)] = gq[f];
        }
        __syncthreads();

        #pragma unroll 1
        for (int s = 0; s < 8; s++) {
            // ---- GEMM1: c1[i][j] = D[32n x 16m], K = l = 128 ----
            float c1[2][2][4];
            #pragma unroll
            for (int i = 0; i < 2; i++)
                #pragma unroll
                for (int j = 0; j < 2; j++)
                    #pragma unroll
                    for (int r = 0; r < 4; r++) c1[i][j][r] = 0.f;

            #pragma unroll
            for (int kk = 0; kk < 8; kk++) {
                uint32_t a[2][4], bfr[4];
                #pragma unroll
                for (int i = 0; i < 2; i++)
                    ldsm4(a[i], sb + (a_row + i * 16u) * 272u + a_colb + kk * 32u);
                ldsm4(bfr, sbi + b_rowb + (uint32_t)(s * 16) * 272u + b_colb + kk * 32u);
                #pragma unroll
                for (int i = 0; i < 2; i++) {
                    mma_bf16(c1[i][0], a[i], bfr[0], bfr[2]);
                    mma_bf16(c1[i][1], a[i], bfr[1], bfr[3]);
                }
            }

            // ---- epilogue: E = 1e-4*exp(-0.1*sqrt(d2)); repack as A frags ----
            uint32_t a2[2][4];
            #pragma unroll
            for (int i = 0; i < 2; i++) {
                #pragma unroll
                for (int j = 0; j < 2; j++) {
                    float2 bn = *(float2*)&bn2s[(c << 7) + s * 16 + j * 8 + 2 * (lane & 3)];
                    float e0 = efun(c1[i][j][0], an2v[i][0], bn.x);
                    float e1 = efun(c1[i][j][1], an2v[i][0], bn.y);
                    float e2 = efun(c1[i][j][2], an2v[i][1], bn.x);
                    float e3 = efun(c1[i][j][3], an2v[i][1], bn.y);
                    a2[i][2 * j]     = pack_bf16(e0, e1);
                    a2[i][2 * j + 1] = pack_bf16(e2, e3);
                }
            }

            // ---- GEMM2: acc2[n, l] += E[n, m16] . img[m16, l] ----
            #pragma unroll
            for (int lb = 0; lb < 8; lb++) {
                uint32_t b2r[4];
                ldsm4t(b2r, sbi + b_rowb + (uint32_t)(s * 16) * 272u
                            + b_colb + lb * 32u);
                #pragma unroll
                for (int i = 0; i < 2; i++) {
                    mma_bf16(acc2[i][2 * lb],     a2[i], b2r[0], b2r[1]);
                    mma_bf16(acc2[i][2 * lb + 1], a2[i], b2r[2], b2r[3]);
                }
            }
        }
        __syncthreads();   // protect simg before next chunk overwrites
    }

    // store alignedT partials: g_part[bid][n][l]
    #pragma unroll
    for (int i = 0; i < 2; i++) {
        int n = w * 32 + i * 16 + (lane >> 2);
        #pragma unroll
        for (int lt = 0; lt < 16; lt++) {
            int l = lt * 8 + 2 * (lane & 3);
            size_t base = (size_t)bid * 32768 + (size_t)n * 128 + l;
            *(float2*)&g_part[base] = make_float2(acc2[i][lt][0], acc2[i][lt][1]);
            *(float2*)&g_part[base + 8 * 128] = make_float2(acc2[i][lt][2], acc2[i][lt][3]);
        }
    }
}

// ================= K2: deterministic reduction of partials =================
__global__ void k_reduce() {
    int id = blockIdx.x * 256 + threadIdx.x;   // id = n*128 + l
    float s = 0.f;
    #pragma unroll 8
    for (int st = 0; st < 128; st++)
        s += g_part[(size_t)st * 32768 + id];
    int n = id >> 7, l = id & 127;
    g_al[l * 256 + n] = s;
}

// ================= K3: t_line + pre1 =================
__global__ void k_prep(const float* __restrict__ w1, const float* __restrict__ b1) {
    __shared__ float tls[8192];   // [l][w]
    int t = threadIdx.x;
    for (int f = t; f < 8192; f += 256) {
        int l = f >> 6, w = f & 63;
        float v = 0.5f * (g_al[l * 256 + 4 * w + 1] + g_al[l * 256 + 4 * w + 2]);
        tls[f] = v;
        g_tline[f] = v;
    }
    __syncthreads();
    for (int f = t; f < 8192; f += 256) {
        int b = f >> 12, o = (f >> 6) & 63, w = f & 63;
        float s = b1[o];
        #pragma unroll 8
        for (int c = 0; c < 64; c++)
            s = fmaf(w1[o * 128 + c], tls[(b * 64 + c) * 64 + w], s);
        g_pre1[f] = s;
    }
}

// ================= K4: per-voxel MLP + gated blend =================
__global__ __launch_bounds__(128) void k_mlp(const float* __restrict__ img,
                                             const float* __restrict__ w1,
                                             const float* __restrict__ w2,
                                             const float* __restrict__ b2,
                                             float* __restrict__ out) {
    __shared__ float sw2[4096];
    __shared__ float sbuf[8192];

    int t = threadIdx.x;
    int bb = blockIdx.x >> 10;
    int m0 = (blockIdx.x & 1023) << 7;
    int w = t & 63;

    for (int f = t; f < 4096; f += 128) {
        int o = f & 63, c = f >> 6;
        sbuf[c * 64 + o] = w1[o * 128 + 64 + c];
        sw2[c * 64 + o] = w2[o * 64 + c];
    }
    __syncthreads();

    const float* ib = img + (size_t)bb * IMG_BSTRIDE + m0 + t;
    const float* pr = g_pre1 + bb * 4096;

    float h[64];
    #pragma unroll
    for (int o = 0; o < 64; o++) h[o] = pr[o * 64 + w];

    #pragma unroll 2
    for (int c = 0; c < 64; c++) {
        float xv = ib[(size_t)c * M_DIM];
        const float4* wr = (const float4*)&sbuf[c * 64];
        #pragma unroll
        for (int q = 0; q < 16; q++) {
            float4 wv = wr[q];
            h[4 * q + 0] = fmaf(wv.x, xv, h[4 * q + 0]);
            h[4 * q + 1] = fmaf(wv.y, xv, h[4 * q + 1]);
            h[4 * q + 2] = fmaf(wv.z, xv, h[4 * q + 2]);
            h[4 * q + 3] = fmaf(wv.w, xv, h[4 * q + 3]);
        }
    }
    __syncthreads();
    #pragma unroll
    for (int o = 0; o < 64; o++) sbuf[o * 128 + t] = fmaxf(h[o], 0.f);
    __syncthreads();

    float g[64];
    #pragma unroll
    for (int o = 0; o < 64; o++) g[o] = __ldg(&b2[o]);

    #pragma unroll 2
    for (int c = 0; c < 64; c++) {
        float hv = sbuf[c * 128 + t];
        const float4* wr = (const float4*)&sw2[c * 64];
        #pragma unroll
        for (int q = 0; q < 16; q++) {
            float4 wv = wr[q];
            g[4 * q + 0] = fmaf(wv.x, hv, g[4 * q + 0]);
            g[4 * q + 1] = fmaf(wv.y, hv, g[4 * q + 1]);
            g[4 * q + 2] = fmaf(wv.z, hv, g[4 * q + 2]);
            g[4 * q + 3] = fmaf(wv.w, hv, g[4 * q + 3]);
        }
    }

    float* ob = out + (size_t)bb * IMG_BSTRIDE + m0 + t;
    const float* tl = g_tline + bb * 4096;
    #pragma unroll
    for (int o = 0; o < 64; o++) {
        float gate = fast_sigmoid(g[o]);
        float xv = ib[(size_t)o * M_DIM];
        float tv = tl[o * 64 + w];
        ob[(size_t)o * M_DIM] = fmaf(gate, tv - xv, xv);
    }
}

// ================= launch =================
extern "C" void kernel_launch(void* const* d_in, const int* in_sizes, int n_in,
                              void* d_out, int out_size) {
    const float* text = (const float*)d_in[0];
    const float* img  = (const float*)d_in[1];
    const float* w1   = (const float*)d_in[2];
    const float* b1   = (const float*)d_in[3];
    const float* w2   = (const float*)d_in[4];
    const float* b2   = (const float*)d_in[5];
    float* out = (float*)d_out;

    cudaFuncSetAttribute(k_prepass, cudaFuncAttributeMaxDynamicSharedMemorySize, 66048);
    cudaFuncSetAttribute(k_fused,   cudaFuncAttributeMaxDynamicSharedMemorySize, 109568);

    k_prepass<<<1025, 256, 66048>>>(img, text);
    k_fused  <<<128, 256, 109568>>>();
    k_reduce <<<128, 256>>>();
    k_prep   <<<1, 256>>>(w1, b1);
    k_mlp    <<<2048, 128>>>(img, w1, w2, b2, out);
}

// round 5
// speedup vs baseline: 3.9088x; 1.8149x over previous
#include <cuda_runtime.h>
#include <cuda_bf16.h>
#include <math.h>
#include <stdint.h>

// ---------------- problem constants ----------------
#define L_DIM   128
#define N_DIM   256
#define M_DIM   131072
#define IMG_BSTRIDE 8388608   // 64*131072

// ---------------- scratch (static device memory; no allocs) ----------------
__device__ __align__(16) unsigned g_text16u[256 * 64];          // bf16 [n][l] pairs
__device__ __align__(16) unsigned g_img16u[(size_t)M_DIM * 64]; // bf16 [m][l] pairs (33.5MB)
__device__ float g_part[128 * 32768];          // alignedT partials [stripe][n][l] (16.8MB)
__device__ float g_bn2[M_DIM];
__device__ float g_an2[N_DIM];
__device__ float g_al[L_DIM * N_DIM];          // aligned [l][n]
__device__ float g_tline[2 * 64 * 64];         // [b][c][w]
__device__ float g_pre1[2 * 64 * 64];          // [b][o][w]

// ---------------- fast math (FMA pipe only) ----------------
__device__ __forceinline__ float fast_exp2(float x) {    // deg-7, for sigmoid
    float fl = floorf(x);
    float f = x - fl;
    float p = 1.5252733804059841e-05f;
    p = fmaf(p, f, 1.5403530393381609e-04f);
    p = fmaf(p, f, 1.3333558146428443e-03f);
    p = fmaf(p, f, 9.6181291076284772e-03f);
    p = fmaf(p, f, 5.5504108664821580e-02f);
    p = fmaf(p, f, 2.4022650695910072e-01f);
    p = fmaf(p, f, 6.9314718055994531e-01f);
    p = fmaf(p, f, 1.0f);
    return __int_as_float(__float_as_int(p) + ((int)fl << 23));
}
__device__ __forceinline__ float fast_exp2_lo(float x) { // deg-4, for E (err ~1e-4 ok)
    float fl = floorf(x);
    float f = x - fl;
    float p = 1.3555305358e-02f;
    p = fmaf(p, f, 5.2058560887e-02f);
    p = fmaf(p, f, 2.4144275178e-01f);
    p = fmaf(p, f, 6.9291652520e-01f);
    p = fmaf(p, f, 1.0000026977f);
    return __int_as_float(__float_as_int(p) + ((int)fl << 23));
}
__device__ __forceinline__ float fast_sigmoid(float x) {
    float ax = fminf(fabsf(x) * 1.4426950408889634f, 120.0f);
    float p = fast_exp2(-ax);
    float d = 1.0f + p;
    float r = __int_as_float(0x7EF311C3 - __float_as_int(d));
    r = r * fmaf(-d, r, 2.0f);
    r = r * fmaf(-d, r, 2.0f);
    r = r * fmaf(-d, r, 2.0f);
    float num = (x >= 0.0f) ? 1.0f : p;
    return num * r;
}
__device__ __forceinline__ float efun(float dot, float an, float bn) {
    float d2 = fmaxf(an + bn - 2.f * dot, 1e-20f);
    float r = __int_as_float(0x5f3759df - (__float_as_int(d2) >> 1));
    r = r * fmaf(-0.5f * d2, r * r, 1.5f);          // 1-Newton rsqrt (E err ~3e-3, fine)
    float cst = d2 * r;
    return 1e-4f * fast_exp2_lo(-0.14426950408889634f * cst);
}

// ---------------- warp MMA helpers ----------------
__device__ __forceinline__ uint32_t smem_u32(const void* p) {
    uint32_t a;
    asm("{ .reg .u64 t; cvta.to.shared.u64 t, %1; cvt.u32.u64 %0, t; }" : "=r"(a) : "l"(p));
    return a;
}
__device__ __forceinline__ void ldsm4(uint32_t* r, uint32_t a) {
    asm volatile("ldmatrix.sync.aligned.m8n8.x4.shared.b16 {%0,%1,%2,%3}, [%4];"
                 : "=r"(r[0]), "=r"(r[1]), "=r"(r[2]), "=r"(r[3]) : "r"(a));
}
__device__ __forceinline__ void ldsm4t(uint32_t* r, uint32_t a) {
    asm volatile("ldmatrix.sync.aligned.m8n8.x4.trans.shared.b16 {%0,%1,%2,%3}, [%4];"
                 : "=r"(r[0]), "=r"(r[1]), "=r"(r[2]), "=r"(r[3]) : "r"(a));
}
__device__ __forceinline__ void mma_bf16(float* d, const uint32_t* a,
                                         uint32_t b0, uint32_t b1) {
    asm volatile("mma.sync.aligned.m16n8k16.row.col.f32.bf16.bf16.f32 "
                 "{%0,%1,%2,%3}, {%4,%5,%6,%7}, {%8,%9}, {%0,%1,%2,%3};"
                 : "+f"(d[0]), "+f"(d[1]), "+f"(d[2]), "+f"(d[3])
                 : "r"(a[0]), "r"(a[1]), "r"(a[2]), "r"(a[3]), "r"(b0), "r"(b1));
}
__device__ __forceinline__ uint32_t pack_bf16(float lo, float hi) {
    uint32_t r;
    asm("cvt.rn.bf16x2.f32 %0, %1, %2;" : "=r"(r) : "f"(hi), "f"(lo));
    return r;
}
__device__ __forceinline__ void split_bf16(float x, uint16_t& h, uint16_t& l) {
    __nv_bfloat16 bh = __float2bfloat16(x);
    float res = x - __bfloat162float(bh);
    __nv_bfloat16 bl = __float2bfloat16(res);
    h = __bfloat16_as_ushort(bh);
    l = __bfloat16_as_ushort(bl);
}
__device__ __forceinline__ uint32_t pack2(uint16_t a, uint16_t b) {
    return (uint32_t)a | ((uint32_t)b << 16);
}

// ================= K0: prepass — bf16 row-major tiles + norms =================
__global__ __launch_bounds__(256) void k_prepass(const float* __restrict__ img,
                                                 const float* __restrict__ text) {
    extern __shared__ float smemf[];   // 128 x 129 floats
    int b = blockIdx.x, t = threadIdx.x;

    if (b < 1024) {
        int m0 = b << 7;
        for (int f = t; f < 16384; f += 256)
            smemf[(f >> 7) * 129 + (f & 127)] =
                img[(size_t)(f >> 7) * M_DIM + m0 + (f & 127)];   // smem [l][m]
        __syncthreads();
        if (t < 128) {
            float s = 0.f;
            #pragma unroll 8
            for (int l = 0; l < 128; l++) {
                float v = smemf[l * 129 + t];
                s = fmaf(v, v, s);
            }
            g_bn2[m0 + t] = s;
        }
        for (int p = t; p < 8192; p += 256) {
            int row = p >> 6, c2 = p & 63;       // m-row, l-pair
            float a0 = smemf[(2 * c2) * 129 + row];
            float a1 = smemf[(2 * c2 + 1) * 129 + row];
            g_img16u[(size_t)(m0 + row) * 64 + c2] = pack_bf16(a0, a1);
        }
    } else {
        for (int p = t; p < 16384; p += 256) {
            int n = p >> 6, c2 = p & 63;
            float v0 = text[(2 * c2) * 256 + n];
            float v1 = text[(2 * c2 + 1) * 256 + n];
            g_text16u[n * 64 + c2] = pack_bf16(v0, v1);
        }
        float s = 0.f;
        #pragma unroll 8
        for (int l = 0; l < 128; l++) {
            float v = text[l * 256 + t];
            s = fmaf(v, v, s);
        }
        g_an2[t] = s;
    }
}

// ================= K1: fused tensor-core pipeline =================
// 256 CTAs: mstripe = bid>>1 (1024 m), nh = bid&1 (128 n). 2 CTAs/SM.
// smem: stext bf16[128][136] @0 | simg bf16[128][136] @34816 | bn2[1024] @69632
//       | an2[128] @73728 | total 74240
__global__ __launch_bounds__(256, 2) void k_fused() {
    extern __shared__ char dsm[];
    const int SIMG = 34816, BN2 = 69632, AN2 = 73728;
    float* bn2s = (float*)(dsm + BN2);
    float* an2s = (float*)(dsm + AN2);

    int t = threadIdx.x;
    int mstripe = blockIdx.x >> 1, nh = blockIdx.x & 1;
    int w = t >> 5, lane = t & 31;
    uint32_t sb = smem_u32(dsm);
    uint32_t sbi = sb + SIMG;

    // persistent loads: text half (32KB), bn2 stripe (4KB), an2 half (512B)
    {
        uint4* stq = (uint4*)dsm;
        const uint4* tq = (const uint4*)g_text16u;
        for (int f = t; f < 2048; f += 256)
            stq[(f >> 4) * 17 + (f & 15)] = tq[(nh << 11) + f];
        #pragma unroll
        for (int i = 0; i < 4; i++)
            bn2s[t + 256 * i] = g_bn2[mstripe * 1024 + t + 256 * i];
        if (t < 128) an2s[t] = g_an2[nh * 128 + t];
    }

    float acc2[16][4];
    #pragma unroll
    for (int lt = 0; lt < 16; lt++)
        #pragma unroll
        for (int r = 0; r < 4; r++) acc2[lt][r] = 0.f;

    __syncthreads();
    float an2v0 = an2s[w * 16 + (lane >> 2)];
    float an2v1 = an2s[w * 16 + (lane >> 2) + 8];

    uint32_t a_row = (uint32_t)(w * 16 + (lane & 15));
    uint32_t a_colb = (uint32_t)((lane >> 4) * 16);
    uint32_t b_rowb = (uint32_t)(lane & 15) * 272u;
    uint32_t b_colb = (uint32_t)((lane >> 4) * 16);

    #pragma unroll 1
    for (int c = 0; c < 8; c++) {
        // load img chunk [128 m][128 l] bf16, padded stride 136
        {
            uint4* siq = (uint4*)(dsm + SIMG);
            const uint4* gq = (const uint4*)g_img16u + (size_t)(mstripe * 8 + c) * 2048;
            for (int f = t; f < 2048; f += 256)
                siq[(f >> 4) * 17 + (f & 15)] = gq[f];
        }
        __syncthreads();

        #pragma unroll 1
        for (int s = 0; s < 8; s++) {
            // ---- GEMM1: D[16n x 16m], K = l = 128 ----
            float c1[2][4];
            #pragma unroll
            for (int j = 0; j < 2; j++)
                #pragma unroll
                for (int r = 0; r < 4; r++) c1[j][r] = 0.f;

            #pragma unroll
            for (int kk = 0; kk < 8; kk++) {
                uint32_t a[4], bfr[4];
                ldsm4(a, sb + a_row * 272u + a_colb + kk * 32u);
                ldsm4(bfr, sbi + b_rowb + (uint32_t)(s * 16) * 272u + b_colb + kk * 32u);
                mma_bf16(c1[0], a, bfr[0], bfr[2]);
                mma_bf16(c1[1], a, bfr[1], bfr[3]);
            }

            // ---- epilogue: E in regs, repack as A frag for GEMM2 ----
            uint32_t a2[4];
            #pragma unroll
            for (int j = 0; j < 2; j++) {
                float2 bn = *(float2*)&bn2s[(c << 7) + s * 16 + j * 8 + 2 * (lane & 3)];
                float e0 = efun(c1[j][0], an2v0, bn.x);
                float e1 = efun(c1[j][1], an2v0, bn.y);
                float e2 = efun(c1[j][2], an2v1, bn.x);
                float e3 = efun(c1[j][3], an2v1, bn.y);
                a2[2 * j]     = pack_bf16(e0, e1);
                a2[2 * j + 1] = pack_bf16(e2, e3);
            }

            // ---- GEMM2: acc2[n, l] += E[n, m16] . img[m16, l] ----
            #pragma unroll
            for (int lb = 0; lb < 8; lb++) {
                uint32_t b2r[4];
                ldsm4t(b2r, sbi + b_rowb + (uint32_t)(s * 16) * 272u + b_colb + lb * 32u);
                mma_bf16(acc2[2 * lb],     a2, b2r[0], b2r[1]);
                mma_bf16(acc2[2 * lb + 1], a2, b2r[2], b2r[3]);
            }
        }
        __syncthreads();
    }

    // store alignedT partials: g_part[mstripe][n][l], n = nh*128 + local
    int nbase = nh * 128 + w * 16 + (lane >> 2);
    #pragma unroll
    for (int lt = 0; lt < 16; lt++) {
        int l = lt * 8 + 2 * (lane & 3);
        size_t base = (size_t)mstripe * 32768 + (size_t)nbase * 128 + l;
        *(float2*)&g_part[base] = make_float2(acc2[lt][0], acc2[lt][1]);
        *(float2*)&g_part[base + 8 * 128] = make_float2(acc2[lt][2], acc2[lt][3]);
    }
}

// ================= K2: deterministic reduction of partials =================
__global__ void k_reduce() {
    int id = blockIdx.x * 64 + threadIdx.x;   // id = n*128 + l
    float s = 0.f;
    #pragma unroll 16
    for (int st = 0; st < 128; st++)
        s += g_part[(size_t)st * 32768 + id];
    int n = id >> 7, l = id & 127;
    g_al[l * 256 + n] = s;
}

// ================= K3a: t_line =================
__global__ void k_tline() {
    int f = blockIdx.x * 256 + threadIdx.x;   // f = l*64 + w
    int l = f >> 6, w = f & 63;
    g_tline[f] = 0.5f * (g_al[l * 256 + 4 * w + 1] + g_al[l * 256 + 4 * w + 2]);
}

// ================= K3b: pre1 = b1 + W1a @ t_line =================
__global__ void k_pre1(const float* __restrict__ w1, const float* __restrict__ b1) {
    int f = blockIdx.x * 256 + threadIdx.x;   // f = b*4096 + o*64 + w
    int b = f >> 12, o = (f >> 6) & 63, w = f & 63;
    float s = __ldg(&b1[o]);
    #pragma unroll 8
    for (int c = 0; c < 64; c++)
        s = fmaf(__ldg(&w1[o * 128 + c]), g_tline[(b * 64 + c) * 64 + w], s);
    g_pre1[f] = s;
}

// ================= K4: per-voxel MLP + gated blend (mma.sync, split-bf16) =====
// 2048 blocks x 256 thr; 128 voxels/block. Split-bf16: D = Ah.Bh + Ah.Bl + Al.Bh
// smem (bytes): XH@0, XL@17408 (64c x 272B) | HH@34816, HL@52224 (64c2 x 272B)
//   | W1H@69632, W1L@78848, W2H@88064, W2L@97280 (64o x 144B) | total 106496
#define SVB 272
#define SWB 144
__global__ __launch_bounds__(256, 2) void k_mlp(const float* __restrict__ img,
                                                const float* __restrict__ w1,
                                                const float* __restrict__ w2,
                                                const float* __restrict__ b2,
                                                float* __restrict__ out) {
    extern __shared__ char dsm[];
    const int XH = 0, XL = 17408, HH = 34816, HL = 52224,
              W1H = 69632, W1L = 78848, W2H = 88064, W2L = 97280;
    uint32_t sb = smem_u32(dsm);

    int t = threadIdx.x;
    int bb = blockIdx.x >> 10;
    int m0 = (blockIdx.x & 1023) << 7;
    int w = t >> 5, lane = t & 31;
    int obase = (w & 3) * 16;
    int vwbase = (w >> 2) * 64;

    // ---- load + split x into XH/XL ----
    for (int f = t; f < 2048; f += 256) {       // 64 c-rows x 32 float4
        int c = f >> 5, v4 = f & 31;
        float4 xv = ((const float4*)(img + (size_t)(bb * 64 + c) * M_DIM + m0))[v4];
        uint16_t h0, l0, h1, l1, h2, l2, h3, l3;
        split_bf16(xv.x, h0, l0); split_bf16(xv.y, h1, l1);
        split_bf16(xv.z, h2, l2); split_bf16(xv.w, h3, l3);
        *(uint2*)(dsm + XH + c * SVB + v4 * 8) = make_uint2(pack2(h0, h1), pack2(h2, h3));
        *(uint2*)(dsm + XL + c * SVB + v4 * 8) = make_uint2(pack2(l0, l1), pack2(l2, l3));
    }
    // ---- load + split weights ----
    for (int f = t; f < 4096; f += 256) {
        int o = f >> 6, c = f & 63;
        uint16_t h, l;
        split_bf16(__ldg(&w1[o * 128 + 64 + c]), h, l);
        *(uint16_t*)(dsm + W1H + o * SWB + c * 2) = h;
        *(uint16_t*)(dsm + W1L + o * SWB + c * 2) = l;
        split_bf16(__ldg(&w2[o * 64 + c]), h, l);
        *(uint16_t*)(dsm + W2H + o * SWB + c * 2) = h;
        *(uint16_t*)(dsm + W2L + o * SWB + c * 2) = l;
    }

    // ---- acc init from pre1 ----
    int orow = obase + (lane >> 2);
    int vcol = 2 * (lane & 3);
    const float* pr = g_pre1 + bb * 4096;
    float acc[8][4];
    #pragma unroll
    for (int j = 0; j < 8; j++) {
        int ws = (vwbase + 8 * j + vcol) & 63;
        acc[j][0] = pr[orow * 64 + ws];
        acc[j][1] = pr[orow * 64 + ws + 1];
        acc[j][2] = pr[(orow + 8) * 64 + ws];
        acc[j][3] = pr[(orow + 8) * 64 + ws + 1];
    }
    __syncthreads();

    uint32_t aw_addr = (uint32_t)(obase + (lane & 15)) * SWB + (uint32_t)((lane >> 4) * 16);
    uint32_t bx_row = (uint32_t)(lane & 15) * SVB;
    uint32_t bx_col = (uint32_t)(vwbase * 2 + (lane >> 4) * 16);

    // ---- layer 1: h = pre1 + W1b @ x ----
    #pragma unroll
    for (int k = 0; k < 4; k++) {
        uint32_t ah[4], al[4];
        ldsm4(ah, sb + W1H + aw_addr + k * 32u);
        ldsm4(al, sb + W1L + aw_addr + k * 32u);
        #pragma unroll
        for (int q = 0; q < 4; q++) {
            uint32_t bh[4], bl[4];
            uint32_t ba = bx_row + (uint32_t)(16 * k) * SVB + bx_col + q * 32u;
            ldsm4t(bh, sb + XH + ba);
            ldsm4t(bl, sb + XL + ba);
            mma_bf16(acc[2 * q], ah, bh[0], bh[1]);
            mma_bf16(acc[2 * q], ah, bl[0], bl[1]);
            mma_bf16(acc[2 * q], al, bh[0], bh[1]);
            mma_bf16(acc[2 * q + 1], ah, bh[2], bh[3]);
            mma_bf16(acc[2 * q + 1], ah, bl[2], bl[3]);
            mma_bf16(acc[2 * q + 1], al, bh[2], bh[3]);
        }
    }

    // ---- relu + split H to smem ----
    #pragma unroll
    for (int j = 0; j < 8; j++) {
        int vox0 = vwbase + 8 * j + vcol;
        uint16_t h0, l0, h1, l1;
        split_bf16(fmaxf(acc[j][0], 0.f), h0, l0);
        split_bf16(fmaxf(acc[j][1], 0.f), h1, l1);
        *(uint32_t*)(dsm + HH + orow * SVB + vox0 * 2) = pack2(h0, h1);
        *(uint32_t*)(dsm + HL + orow * SVB + vox0 * 2) = pack2(l0, l1);
        split_bf16(fmaxf(acc[j][2], 0.f), h0, l0);
        split_bf16(fmaxf(acc[j][3], 0.f), h1, l1);
        *(uint32_t*)(dsm + HH + (orow + 8) * SVB + vox0 * 2) = pack2(h0, h1);
        *(uint32_t*)(dsm + HL + (orow + 8) * SVB + vox0 * 2) = pack2(l0, l1);
    }
    __syncthreads();

    // ---- layer 2: g = b2 + W2 @ H ----
    float bv0 = __ldg(&b2[orow]), bv1 = __ldg(&b2[orow + 8]);
    #pragma unroll
    for (int j = 0; j < 8; j++) {
        acc[j][0] = bv0; acc[j][1] = bv0;
        acc[j][2] = bv1; acc[j][3] = bv1;
    }
    #pragma unroll
    for (int k = 0; k < 4; k++) {
        uint32_t ah[4], al[4];
        ldsm4(ah, sb + W2H + aw_addr + k * 32u);
        ldsm4(al, sb + W2L + aw_addr + k * 32u);
        #pragma unroll
        for (int q = 0; q < 4; q++) {
            uint32_t bh[4], bl[4];
            uint32_t ba = bx_row + (uint32_t)(16 * k) * SVB + bx_col + q * 32u;
            ldsm4t(bh, sb + HH + ba);
            ldsm4t(bl, sb + HL + ba);
            mma_bf16(acc[2 * q], ah, bh[0], bh[1]);
            mma_bf16(acc[2 * q], ah, bl[0], bl[1]);
            mma_bf16(acc[2 * q], al, bh[0], bh[1]);
            mma_bf16(acc[2 * q + 1], ah, bh[2], bh[3]);
            mma_bf16(acc[2 * q + 1], ah, bl[2], bl[3]);
            mma_bf16(acc[2 * q + 1], al, bh[2], bh[3]);
        }
    }

    // ---- gate + blend + store ----
    const float* tl = g_tline + bb * 4096;
    #pragma unroll
    for (int j = 0; j < 8; j++) {
        int vox0 = vwbase + 8 * j + vcol;
        int ws = vox0 & 63;
        #pragma unroll
        for (int half = 0; half < 2; half++) {
            int row = orow + 8 * half;
            size_t gidx = (size_t)(bb * 64 + row) * M_DIM + m0 + vox0;
            float2 xv = *(const float2*)(img + gidx);
            float2 tv = *(const float2*)(tl + row * 64 + ws);
            float g0 = fast_sigmoid(acc[j][2 * half]);
            float g1 = fast_sigmoid(acc[j][2 * half + 1]);
            float2 ov;
            ov.x = fmaf(g0, tv.x - xv.x, xv.x);
            ov.y = fmaf(g1, tv.y - xv.y, xv.y);
            *(float2*)(out + gidx) = ov;
        }
    }
}

// ================= launch =================
extern "C" void kernel_launch(void* const* d_in, const int* in_sizes, int n_in,
                              void* d_out, int out_size) {
    const float* text = (const float*)d_in[0];
    const float* img  = (const float*)d_in[1];
    const float* w1   = (const float*)d_in[2];
    const float* b1   = (const float*)d_in[3];
    const float* w2   = (const float*)d_in[4];
    const float* b2   = (const float*)d_in[5];
    float* out = (float*)d_out;

    cudaFuncSetAttribute(k_prepass, cudaFuncAttributeMaxDynamicSharedMemorySize, 66048);
    cudaFuncSetAttribute(k_fused,   cudaFuncAttributeMaxDynamicSharedMemorySize, 74240);
    cudaFuncSetAttribute(k_mlp,     cudaFuncAttributeMaxDynamicSharedMemorySize, 106496);

    k_prepass<<<1025, 256, 66048>>>(img, text);
    k_fused  <<<256, 256, 74240>>>();
    k_reduce <<<512, 64>>>();
    k_tline  <<<32, 256>>>();
    k_pre1   <<<32, 256>>>(w1, b1);
    k_mlp    <<<2048, 256, 106496>>>(img, w1, w2, b2, out);
}

// round 6
// speedup vs baseline: 4.2560x; 1.0888x over previous
#include <cuda_runtime.h>
#include <cuda_bf16.h>
#include <cuda_fp16.h>
#include <math.h>
#include <stdint.h>

// ---------------- problem constants ----------------
#define L_DIM   128
#define N_DIM   256
#define M_DIM   131072
#define IMG_BSTRIDE 8388608   // 64*131072

// ---------------- scratch (static device memory; no allocs) ----------------
__device__ __align__(16) unsigned g_text16u[256 * 64];          // bf16 [n][l] pairs
__device__ __align__(16) unsigned g_img16u[(size_t)M_DIM * 64]; // bf16 [m][l] pairs (33.5MB)
__device__ float g_part[128 * 32768];          // alignedT partials [stripe][n][l] (16.8MB)
__device__ float g_bn2[M_DIM];
__device__ float g_an2[N_DIM];
__device__ float g_al[L_DIM * N_DIM];          // aligned [l][n]
__device__ float g_tline[2 * 64 * 64];         // [b][c][w]
__device__ float g_pre1[2 * 64 * 64];          // [b][o][w]

// ---------------- fast math (FMA pipe only) ----------------
__device__ __forceinline__ float fast_exp2(float x) {    // deg-7, for sigmoid
    float fl = floorf(x);
    float f = x - fl;
    float p = 1.5252733804059841e-05f;
    p = fmaf(p, f, 1.5403530393381609e-04f);
    p = fmaf(p, f, 1.3333558146428443e-03f);
    p = fmaf(p, f, 9.6181291076284772e-03f);
    p = fmaf(p, f, 5.5504108664821580e-02f);
    p = fmaf(p, f, 2.4022650695910072e-01f);
    p = fmaf(p, f, 6.9314718055994531e-01f);
    p = fmaf(p, f, 1.0f);
    return __int_as_float(__float_as_int(p) + ((int)fl << 23));
}
__device__ __forceinline__ float fast_exp2_lo(float x) { // deg-4, for E
    float fl = floorf(x);
    float f = x - fl;
    float p = 1.3555305358e-02f;
    p = fmaf(p, f, 5.2058560887e-02f);
    p = fmaf(p, f, 2.4144275178e-01f);
    p = fmaf(p, f, 6.9291652520e-01f);
    p = fmaf(p, f, 1.0000026977f);
    return __int_as_float(__float_as_int(p) + ((int)fl << 23));
}
__device__ __forceinline__ float fast_sigmoid(float x) {
    float ax = fminf(fabsf(x) * 1.4426950408889634f, 120.0f);
    float p = fast_exp2(-ax);
    float d = 1.0f + p;
    float r = __int_as_float(0x7EF311C3 - __float_as_int(d));
    r = r * fmaf(-d, r, 2.0f);
    r = r * fmaf(-d, r, 2.0f);
    r = r * fmaf(-d, r, 2.0f);
    float num = (x >= 0.0f) ? 1.0f : p;
    return num * r;
}
__device__ __forceinline__ float efun(float dot, float an, float bn) {
    float d2 = fmaxf(an + bn - 2.f * dot, 1e-20f);
    float r = __int_as_float(0x5f3759df - (__float_as_int(d2) >> 1));
    r = r * fmaf(-0.5f * d2, r * r, 1.5f);
    float cst = d2 * r;
    return 1e-4f * fast_exp2_lo(-0.14426950408889634f * cst);
}

// ---------------- warp MMA helpers ----------------
__device__ __forceinline__ uint32_t smem_u32(const void* p) {
    uint32_t a;
    asm("{ .reg .u64 t; cvta.to.shared.u64 t, %1; cvt.u32.u64 %0, t; }" : "=r"(a) : "l"(p));
    return a;
}
__device__ __forceinline__ void ldsm4(uint32_t* r, uint32_t a) {
    asm volatile("ldmatrix.sync.aligned.m8n8.x4.shared.b16 {%0,%1,%2,%3}, [%4];"
                 : "=r"(r[0]), "=r"(r[1]), "=r"(r[2]), "=r"(r[3]) : "r"(a));
}
__device__ __forceinline__ void ldsm4t(uint32_t* r, uint32_t a) {
    asm volatile("ldmatrix.sync.aligned.m8n8.x4.trans.shared.b16 {%0,%1,%2,%3}, [%4];"
                 : "=r"(r[0]), "=r"(r[1]), "=r"(r[2]), "=r"(r[3]) : "r"(a));
}
__device__ __forceinline__ void mma_bf16(float* d, const uint32_t* a,
                                         uint32_t b0, uint32_t b1) {
    asm volatile("mma.sync.aligned.m16n8k16.row.col.f32.bf16.bf16.f32 "
                 "{%0,%1,%2,%3}, {%4,%5,%6,%7}, {%8,%9}, {%0,%1,%2,%3};"
                 : "+f"(d[0]), "+f"(d[1]), "+f"(d[2]), "+f"(d[3])
                 : "r"(a[0]), "r"(a[1]), "r"(a[2]), "r"(a[3]), "r"(b0), "r"(b1));
}
__device__ __forceinline__ void mma_f16(float* d, const uint32_t* a,
                                        uint32_t b0, uint32_t b1) {
    asm volatile("mma.sync.aligned.m16n8k16.row.col.f32.f16.f16.f32 "
                 "{%0,%1,%2,%3}, {%4,%5,%6,%7}, {%8,%9}, {%0,%1,%2,%3};"
                 : "+f"(d[0]), "+f"(d[1]), "+f"(d[2]), "+f"(d[3])
                 : "r"(a[0]), "r"(a[1]), "r"(a[2]), "r"(a[3]), "r"(b0), "r"(b1));
}
__device__ __forceinline__ uint32_t pack_bf16(float lo, float hi) {
    uint32_t r;
    asm("cvt.rn.bf16x2.f32 %0, %1, %2;" : "=r"(r) : "f"(hi), "f"(lo));
    return r;
}
__device__ __forceinline__ uint32_t pack_f16(float lo, float hi) {
    uint32_t r;
    asm("cvt.rn.f16x2.f32 %0, %1, %2;" : "=r"(r) : "f"(hi), "f"(lo));
    return r;
}
__device__ __forceinline__ void cp_async16(uint32_t daddr, const void* gptr) {
    asm volatile("cp.async.ca.shared.global [%0], [%1], 16;"
                 :: "r"(daddr), "l"(gptr) : "memory");
}

// ================= K0: prepass — bf16 row-major tiles + norms =================
__global__ __launch_bounds__(256) void k_prepass(const float* __restrict__ img,
                                                 const float* __restrict__ text) {
    extern __shared__ float smemf[];   // 128 x 129 floats
    int b = blockIdx.x, t = threadIdx.x;

    if (b < 1024) {
        int m0 = b << 7;
        for (int f = t; f < 16384; f += 256)
            smemf[(f >> 7) * 129 + (f & 127)] =
                img[(size_t)(f >> 7) * M_DIM + m0 + (f & 127)];   // smem [l][m]
        __syncthreads();
        if (t < 128) {
            float s = 0.f;
            #pragma unroll 8
            for (int l = 0; l < 128; l++) {
                float v = smemf[l * 129 + t];
                s = fmaf(v, v, s);
            }
            g_bn2[m0 + t] = s;
        }
        for (int p = t; p < 8192; p += 256) {
            int row = p >> 6, c2 = p & 63;       // m-row, l-pair
            float a0 = smemf[(2 * c2) * 129 + row];
            float a1 = smemf[(2 * c2 + 1) * 129 + row];
            g_img16u[(size_t)(m0 + row) * 64 + c2] = pack_bf16(a0, a1);
        }
    } else {
        for (int p = t; p < 16384; p += 256) {
            int n = p >> 6, c2 = p & 63;
            float v0 = text[(2 * c2) * 256 + n];
            float v1 = text[(2 * c2 + 1) * 256 + n];
            g_text16u[n * 64 + c2] = pack_bf16(v0, v1);
        }
        float s = 0.f;
        #pragma unroll 8
        for (int l = 0; l < 128; l++) {
            float v = text[l * 256 + t];
            s = fmaf(v, v, s);
        }
        g_an2[t] = s;
    }
}

// ================= K1: fused tensor-core pipeline (cp.async double-buffered) ==
// 256 CTAs: mstripe = bid>>1 (1024 m), nh = bid&1 (128 n). 2 CTAs/SM.
// smem: stext[128][136]bf16 @0 | simg buf0 @34816 | buf1 @69632 | bn2 @104448
//       | an2 @108544 | total 109056
__global__ __launch_bounds__(256, 2) void k_fused() {
    extern __shared__ char dsm[];
    const int SIMG0 = 34816, SIMG1 = 69632, BN2 = 104448, AN2 = 108544;
    float* bn2s = (float*)(dsm + BN2);
    float* an2s = (float*)(dsm + AN2);

    int t = threadIdx.x;
    int mstripe = blockIdx.x >> 1, nh = blockIdx.x & 1;
    int w = t >> 5, lane = t & 31;
    uint32_t sb = smem_u32(dsm);

    // persistent loads
    {
        uint4* stq = (uint4*)dsm;
        const uint4* tq = (const uint4*)g_text16u;
        for (int f = t; f < 2048; f += 256)
            stq[(f >> 4) * 17 + (f & 15)] = tq[(nh << 11) + f];
        #pragma unroll
        for (int i = 0; i < 4; i++)
            bn2s[t + 256 * i] = g_bn2[mstripe * 1024 + t + 256 * i];
        if (t < 128) an2s[t] = g_an2[nh * 128 + t];
    }

    // prologue: async-load chunk 0 into buf 0
    {
        const uint4* gq = (const uint4*)g_img16u + (size_t)(mstripe * 8) * 2048;
        #pragma unroll
        for (int r = 0; r < 8; r++) {
            int f = t + 256 * r;
            cp_async16(sb + SIMG0 + (uint32_t)((f >> 4) * 17 + (f & 15)) * 16u, gq + f);
        }
        asm volatile("cp.async.commit_group;" ::: "memory");
    }

    float acc2[16][4];
    #pragma unroll
    for (int lt = 0; lt < 16; lt++)
        #pragma unroll
        for (int r = 0; r < 4; r++) acc2[lt][r] = 0.f;

    __syncthreads();
    float an2v0 = an2s[w * 16 + (lane >> 2)];
    float an2v1 = an2s[w * 16 + (lane >> 2) + 8];

    uint32_t a_row = (uint32_t)(w * 16 + (lane & 15));
    uint32_t a_colb = (uint32_t)((lane >> 4) * 16);
    uint32_t b_rowb = (uint32_t)(lane & 15) * 272u;
    uint32_t b_colb = (uint32_t)((lane >> 4) * 16);

    #pragma unroll 1
    for (int c = 0; c < 8; c++) {
        // issue next chunk into the other buffer
        if (c < 7) {
            uint32_t dst = sb + (((c + 1) & 1) ? SIMG1 : SIMG0);
            const uint4* gq = (const uint4*)g_img16u
                            + (size_t)(mstripe * 8 + c + 1) * 2048;
            #pragma unroll
            for (int r = 0; r < 8; r++) {
                int f = t + 256 * r;
                cp_async16(dst + (uint32_t)((f >> 4) * 17 + (f & 15)) * 16u, gq + f);
            }
            asm volatile("cp.async.commit_group;" ::: "memory");
            asm volatile("cp.async.wait_group 1;" ::: "memory");
        } else {
            asm volatile("cp.async.wait_group 0;" ::: "memory");
        }
        __syncthreads();
        uint32_t sbi = sb + ((c & 1) ? SIMG1 : SIMG0);

        #pragma unroll 1
        for (int s = 0; s < 8; s++) {
            // ---- GEMM1: D[16n x 16m], K = l = 128 ----
            float c1[2][4];
            #pragma unroll
            for (int j = 0; j < 2; j++)
                #pragma unroll
                for (int r = 0; r < 4; r++) c1[j][r] = 0.f;

            #pragma unroll
            for (int kk = 0; kk < 8; kk++) {
                uint32_t a[4], bfr[4];
                ldsm4(a, sb + a_row * 272u + a_colb + kk * 32u);
                ldsm4(bfr, sbi + b_rowb + (uint32_t)(s * 16) * 272u + b_colb + kk * 32u);
                mma_bf16(c1[0], a, bfr[0], bfr[2]);
                mma_bf16(c1[1], a, bfr[1], bfr[3]);
            }

            // ---- epilogue: E in regs, repack as A frag for GEMM2 ----
            uint32_t a2[4];
            #pragma unroll
            for (int j = 0; j < 2; j++) {
                float2 bn = *(float2*)&bn2s[(c << 7) + s * 16 + j * 8 + 2 * (lane & 3)];
                float e0 = efun(c1[j][0], an2v0, bn.x);
                float e1 = efun(c1[j][1], an2v0, bn.y);
                float e2 = efun(c1[j][2], an2v1, bn.x);
                float e3 = efun(c1[j][3], an2v1, bn.y);
                a2[2 * j]     = pack_bf16(e0, e1);
                a2[2 * j + 1] = pack_bf16(e2, e3);
            }

            // ---- GEMM2: acc2[n, l] += E[n, m16] . img[m16, l] ----
            #pragma unroll
            for (int lb = 0; lb < 8; lb++) {
                uint32_t b2r[4];
                ldsm4t(b2r, sbi + b_rowb + (uint32_t)(s * 16) * 272u + b_colb + lb * 32u);
                mma_bf16(acc2[2 * lb],     a2, b2r[0], b2r[1]);
                mma_bf16(acc2[2 * lb + 1], a2, b2r[2], b2r[3]);
            }
        }
        __syncthreads();
    }

    // store alignedT partials: g_part[mstripe][n][l], n = nh*128 + local
    int nbase = nh * 128 + w * 16 + (lane >> 2);
    #pragma unroll
    for (int lt = 0; lt < 16; lt++) {
        int l = lt * 8 + 2 * (lane & 3);
        size_t base = (size_t)mstripe * 32768 + (size_t)nbase * 128 + l;
        *(float2*)&g_part[base] = make_float2(acc2[lt][0], acc2[lt][1]);
        *(float2*)&g_part[base + 8 * 128] = make_float2(acc2[lt][2], acc2[lt][3]);
    }
}

// ================= K2: deterministic reduction of partials =================
__global__ void k_reduce() {
    int id = blockIdx.x * 64 + threadIdx.x;   // id = n*128 + l
    float s = 0.f;
    #pragma unroll 16
    for (int st = 0; st < 128; st++)
        s += g_part[(size_t)st * 32768 + id];
    int n = id >> 7, l = id & 127;
    g_al[l * 256 + n] = s;
}

// ================= K3a: t_line =================
__global__ void k_tline() {
    int f = blockIdx.x * 256 + threadIdx.x;   // f = l*64 + w
    int l = f >> 6, w = f & 63;
    g_tline[f] = 0.5f * (g_al[l * 256 + 4 * w + 1] + g_al[l * 256 + 4 * w + 2]);
}

// ================= K3b: pre1 = b1 + W1a @ t_line =================
__global__ void k_pre1(const float* __restrict__ w1, const float* __restrict__ b1) {
    int f = blockIdx.x * 256 + threadIdx.x;   // f = b*4096 + o*64 + w
    int b = f >> 12, o = (f >> 6) & 63, w = f & 63;
    float s = __ldg(&b1[o]);
    #pragma unroll 8
    for (int c = 0; c < 64; c++)
        s = fmaf(__ldg(&w1[o * 128 + c]), g_tline[(b * 64 + c) * 64 + w], s);
    g_pre1[f] = s;
}

// ================= K4: per-voxel MLP + gated blend (fp16 mma) =================
// 2048 blocks x 256 thr; 128 voxels/block. Single fp16 path (rel err ~1e-4).
// smem: X16@0 (64c x 272B), H16@17408, W1@34816 (64o x 144B), W2@44032; tot 53248
#define SVB 272
#define SWB 144
__global__ __launch_bounds__(256, 2) void k_mlp(const float* __restrict__ img,
                                                const float* __restrict__ w1,
                                                const float* __restrict__ w2,
                                                const float* __restrict__ b2,
                                                float* __restrict__ out) {
    extern __shared__ char dsm[];
    const int X16 = 0, H16 = 17408, W1O = 34816, W2O = 44032;
    uint32_t sb = smem_u32(dsm);

    int t = threadIdx.x;
    int bb = blockIdx.x >> 10;
    int m0 = (blockIdx.x & 1023) << 7;
    int w = t >> 5, lane = t & 31;
    int obase = (w & 3) * 16;
    int vwbase = (w >> 2) * 64;

    // ---- load x -> fp16 smem ----
    for (int f = t; f < 2048; f += 256) {       // 64 c-rows x 32 float4
        int c = f >> 5, v4 = f & 31;
        float4 xv = ((const float4*)(img + (size_t)(bb * 64 + c) * M_DIM + m0))[v4];
        *(uint2*)(dsm + X16 + c * SVB + v4 * 8) =
            make_uint2(pack_f16(xv.x, xv.y), pack_f16(xv.z, xv.w));
    }
    // ---- load weights -> fp16 smem ----
    for (int f = t; f < 4096; f += 256) {
        int o = f >> 6, c = f & 63;
        *(uint16_t*)(dsm + W1O + o * SWB + c * 2) =
            __half_as_ushort(__float2half_rn(__ldg(&w1[o * 128 + 64 + c])));
        *(uint16_t*)(dsm + W2O + o * SWB + c * 2) =
            __half_as_ushort(__float2half_rn(__ldg(&w2[o * 64 + c])));
    }

    // ---- acc init from pre1 ----
    int orow = obase + (lane >> 2);
    int vcol = 2 * (lane & 3);
    const float* pr = g_pre1 + bb * 4096;
    float acc[8][4];
    #pragma unroll
    for (int j = 0; j < 8; j++) {
        int ws = (vwbase + 8 * j + vcol) & 63;
        acc[j][0] = pr[orow * 64 + ws];
        acc[j][1] = pr[orow * 64 + ws + 1];
        acc[j][2] = pr[(orow + 8) * 64 + ws];
        acc[j][3] = pr[(orow + 8) * 64 + ws + 1];
    }
    __syncthreads();

    uint32_t aw_addr = (uint32_t)(obase + (lane & 15)) * SWB + (uint32_t)((lane >> 4) * 16);
    uint32_t bx_row = (uint32_t)(lane & 15) * SVB;
    uint32_t bx_col = (uint32_t)(vwbase * 2 + (lane >> 4) * 16);

    // ---- layer 1: h = pre1 + W1b @ x ----
    #pragma unroll
    for (int k = 0; k < 4; k++) {
        uint32_t a[4];
        ldsm4(a, sb + W1O + aw_addr + k * 32u);
        #pragma unroll
        for (int q = 0; q < 4; q++) {
            uint32_t bx[4];
            ldsm4t(bx, sb + X16 + bx_row + (uint32_t)(16 * k) * SVB + bx_col + q * 32u);
            mma_f16(acc[2 * q],     a, bx[0], bx[1]);
            mma_f16(acc[2 * q + 1], a, bx[2], bx[3]);
        }
    }

    // ---- relu -> fp16 H smem ----
    #pragma unroll
    for (int j = 0; j < 8; j++) {
        int vox0 = vwbase + 8 * j + vcol;
        *(uint32_t*)(dsm + H16 + orow * SVB + vox0 * 2) =
            pack_f16(fmaxf(acc[j][0], 0.f), fmaxf(acc[j][1], 0.f));
        *(uint32_t*)(dsm + H16 + (orow + 8) * SVB + vox0 * 2) =
            pack_f16(fmaxf(acc[j][2], 0.f), fmaxf(acc[j][3], 0.f));
    }
    __syncthreads();

    // ---- layer 2: g = b2 + W2 @ H ----
    float bv0 = __ldg(&b2[orow]), bv1 = __ldg(&b2[orow + 8]);
    #pragma unroll
    for (int j = 0; j < 8; j++) {
        acc[j][0] = bv0; acc[j][1] = bv0;
        acc[j][2] = bv1; acc[j][3] = bv1;
    }
    #pragma unroll
    for (int k = 0; k < 4; k++) {
        uint32_t a[4];
        ldsm4(a, sb + W2O + aw_addr + k * 32u);
        #pragma unroll
        for (int q = 0; q < 4; q++) {
            uint32_t bh[4];
            ldsm4t(bh, sb + H16 + bx_row + (uint32_t)(16 * k) * SVB + bx_col + q * 32u);
            mma_f16(acc[2 * q],     a, bh[0], bh[1]);
            mma_f16(acc[2 * q + 1], a, bh[2], bh[3]);
        }
    }

    // ---- gate + blend + store ----
    const float* tl = g_tline + bb * 4096;
    #pragma unroll
    for (int j = 0; j < 8; j++) {
        int vox0 = vwbase + 8 * j + vcol;
        int ws = vox0 & 63;
        #pragma unroll
        for (int half = 0; half < 2; half++) {
            int row = orow + 8 * half;
            size_t gidx = (size_t)(bb * 64 + row) * M_DIM + m0 + vox0;
            float2 xv = *(const float2*)(img + gidx);
            float2 tv = *(const float2*)(tl + row * 64 + ws);
            float g0 = fast_sigmoid(acc[j][2 * half]);
            float g1 = fast_sigmoid(acc[j][2 * half + 1]);
            float2 ov;
            ov.x = fmaf(g0, tv.x - xv.x, xv.x);
            ov.y = fmaf(g1, tv.y - xv.y, xv.y);
            *(float2*)(out + gidx) = ov;
        }
    }
}

// ================= launch =================
extern "C" void kernel_launch(void* const* d_in, const int* in_sizes, int n_in,
                              void* d_out, int out_size) {
    const float* text = (const float*)d_in[0];
    const float* img  = (const float*)d_in[1];
    const float* w1   = (const float*)d_in[2];
    const float* b1   = (const float*)d_in[3];
    const float* w2   = (const float*)d_in[4];
    const float* b2   = (const float*)d_in[5];
    float* out = (float*)d_out;

    cudaFuncSetAttribute(k_prepass, cudaFuncAttributeMaxDynamicSharedMemorySize, 66048);
    cudaFuncSetAttribute(k_fused,   cudaFuncAttributeMaxDynamicSharedMemorySize, 109056);
    cudaFuncSetAttribute(k_mlp,     cudaFuncAttributeMaxDynamicSharedMemorySize, 53248);

    k_prepass<<<1025, 256, 66048>>>(img, text);
    k_fused  <<<256, 256, 109056>>>();
    k_reduce <<<512, 64>>>();
    k_tline  <<<32, 256>>>();
    k_pre1   <<<32, 256>>>(w1, b1);
    k_mlp    <<<2048, 256, 53248>>>(img, w1, w2, b2, out);
}

// round 7
// speedup vs baseline: 5.4050x; 1.2700x over previous
#include <cuda_runtime.h>
#include <cuda_bf16.h>
#include <cuda_fp16.h>
#include <math.h>
#include <stdint.h>

// ---------------- problem constants ----------------
#define L_DIM   128
#define N_DIM   256
#define M_DIM   131072
#define IMG_BSTRIDE 8388608   // 64*131072

// Only n in {4w+1, 4w+2 : w in [0,64)} feed the output (trilinear interp taps).
// Packed sel index s in [0,128): n = 4*(s>>1) + 1 + (s&1).

// ---------------- scratch (static device memory; no allocs) ----------------
__device__ __align__(16) unsigned g_text16u[128 * 64];          // bf16 [sel-n][l] pairs
__device__ __align__(16) unsigned g_img16u[(size_t)128 * 65536]; // bf16 [l][m] pairs (33.5MB)
__device__ float g_part[256 * 16384];          // alignedT partials [stripe][sel-n][l]
__device__ float g_bn2[M_DIM];
__device__ float g_an2[128];                   // sel-n squared norms
__device__ float g_alsel[16384];               // aligned [sel-n][l]
__device__ float g_tline[2 * 64 * 64];         // [b][c][w]
__device__ float g_pre1[2 * 64 * 64];          // [b][o][w]

// ---------------- fast math (FMA pipe only) ----------------
__device__ __forceinline__ float fast_exp2(float x) {    // deg-7, for sigmoid
    float fl = floorf(x);
    float f = x - fl;
    float p = 1.5252733804059841e-05f;
    p = fmaf(p, f, 1.5403530393381609e-04f);
    p = fmaf(p, f, 1.3333558146428443e-03f);
    p = fmaf(p, f, 9.6181291076284772e-03f);
    p = fmaf(p, f, 5.5504108664821580e-02f);
    p = fmaf(p, f, 2.4022650695910072e-01f);
    p = fmaf(p, f, 6.9314718055994531e-01f);
    p = fmaf(p, f, 1.0f);
    return __int_as_float(__float_as_int(p) + ((int)fl << 23));
}
__device__ __forceinline__ float fast_exp2_lo(float x) { // deg-4, for E
    float fl = floorf(x);
    float f = x - fl;
    float p = 1.3555305358e-02f;
    p = fmaf(p, f, 5.2058560887e-02f);
    p = fmaf(p, f, 2.4144275178e-01f);
    p = fmaf(p, f, 6.9291652520e-01f);
    p = fmaf(p, f, 1.0000026977f);
    return __int_as_float(__float_as_int(p) + ((int)fl << 23));
}
__device__ __forceinline__ float fast_sigmoid(float x) {
    float ax = fminf(fabsf(x) * 1.4426950408889634f, 120.0f);
    float p = fast_exp2(-ax);
    float d = 1.0f + p;
    float r = __int_as_float(0x7EF311C3 - __float_as_int(d));
    r = r * fmaf(-d, r, 2.0f);
    r = r * fmaf(-d, r, 2.0f);
    r = r * fmaf(-d, r, 2.0f);
    float num = (x >= 0.0f) ? 1.0f : p;
    return num * r;
}
__device__ __forceinline__ float efun(float dot, float an, float bn) {
    float d2 = fmaxf(an + bn - 2.f * dot, 1e-20f);
    float r = __int_as_float(0x5f3759df - (__float_as_int(d2) >> 1));
    r = r * fmaf(-0.5f * d2, r * r, 1.5f);
    float cst = d2 * r;
    return 1e-4f * fast_exp2_lo(-0.14426950408889634f * cst);
}

// ---------------- warp MMA helpers ----------------
__device__ __forceinline__ uint32_t smem_u32(const void* p) {
    uint32_t a;
    asm("{ .reg .u64 t; cvta.to.shared.u64 t, %1; cvt.u32.u64 %0, t; }" : "=r"(a) : "l"(p));
    return a;
}
__device__ __forceinline__ void ldsm4(uint32_t* r, uint32_t a) {
    asm volatile("ldmatrix.sync.aligned.m8n8.x4.shared.b16 {%0,%1,%2,%3}, [%4];"
                 : "=r"(r[0]), "=r"(r[1]), "=r"(r[2]), "=r"(r[3]) : "r"(a));
}
__device__ __forceinline__ void ldsm4t(uint32_t* r, uint32_t a) {
    asm volatile("ldmatrix.sync.aligned.m8n8.x4.trans.shared.b16 {%0,%1,%2,%3}, [%4];"
                 : "=r"(r[0]), "=r"(r[1]), "=r"(r[2]), "=r"(r[3]) : "r"(a));
}
__device__ __forceinline__ void mma_bf16(float* d, const uint32_t* a,
                                         uint32_t b0, uint32_t b1) {
    asm volatile("mma.sync.aligned.m16n8k16.row.col.f32.bf16.bf16.f32 "
                 "{%0,%1,%2,%3}, {%4,%5,%6,%7}, {%8,%9}, {%0,%1,%2,%3};"
                 : "+f"(d[0]), "+f"(d[1]), "+f"(d[2]), "+f"(d[3])
                 : "r"(a[0]), "r"(a[1]), "r"(a[2]), "r"(a[3]), "r"(b0), "r"(b1));
}
__device__ __forceinline__ void mma_f16(float* d, const uint32_t* a,
                                        uint32_t b0, uint32_t b1) {
    asm volatile("mma.sync.aligned.m16n8k16.row.col.f32.f16.f16.f32 "
                 "{%0,%1,%2,%3}, {%4,%5,%6,%7}, {%8,%9}, {%0,%1,%2,%3};"
                 : "+f"(d[0]), "+f"(d[1]), "+f"(d[2]), "+f"(d[3])
                 : "r"(a[0]), "r"(a[1]), "r"(a[2]), "r"(a[3]), "r"(b0), "r"(b1));
}
__device__ __forceinline__ uint32_t pack_bf16(float lo, float hi) {
    uint32_t r;
    asm("cvt.rn.bf16x2.f32 %0, %1, %2;" : "=r"(r) : "f"(hi), "f"(lo));
    return r;
}
__device__ __forceinline__ uint32_t pack_f16(float lo, float hi) {
    uint32_t r;
    asm("cvt.rn.f16x2.f32 %0, %1, %2;" : "=r"(r) : "f"(hi), "f"(lo));
    return r;
}
__device__ __forceinline__ void cp_async16(uint32_t daddr, const void* gptr) {
    asm volatile("cp.async.ca.shared.global [%0], [%1], 16;"
                 :: "r"(daddr), "l"(gptr) : "memory");
}

// ================= K0: prepass — streaming convert + norms =================
// blocks 0..255: img fp32 [l][m] -> bf16 [l][m] + bn2 (pure streaming, no smem)
// block 256: text sel columns -> g_text16u [sel][l] + an2
__global__ __launch_bounds__(256) void k_prepass(const float* __restrict__ img,
                                                 const float* __restrict__ text) {
    int b = blockIdx.x, t = threadIdx.x;
    if (b < 256) {
        int m2 = b * 256 + t;                 // m-pair index, 65536 total
        const float2* ip = (const float2*)img;
        float s0 = 0.f, s1 = 0.f;
        #pragma unroll 4
        for (int l = 0; l < 128; l++) {
            float2 v = ip[(size_t)l * 65536 + m2];
            g_img16u[(size_t)l * 65536 + m2] = pack_bf16(v.x, v.y);
            s0 = fmaf(v.x, v.x, s0);
            s1 = fmaf(v.y, v.y, s1);
        }
        *(float2*)&g_bn2[2 * m2] = make_float2(s0, s1);
    } else {
        for (int p = t; p < 8192; p += 256) {
            int s = p >> 6, c2 = p & 63;
            int n = 4 * (s >> 1) + 1 + (s & 1);
            g_text16u[p] = pack_bf16(text[(2 * c2) * 256 + n],
                                     text[(2 * c2 + 1) * 256 + n]);
        }
        if (t < 128) {
            int n = 4 * (t >> 1) + 1 + (t & 1);
            float s = 0.f;
            #pragma unroll 8
            for (int l = 0; l < 128; l++) {
                float v = text[l * 256 + n];
                s = fmaf(v, v, s);
            }
            g_an2[t] = s;
        }
    }
}

// ================= K1: fused tensor-core pipeline (sel-n, halved work) ========
// 256 CTAs x 256 thr, 2/SM. CTA = m-stripe of 512 (4 chunks of 128 m).
// smem: stext[128 sel][136 pairs] @0 | img buf0 @34816 | buf1 @69632 (both
//       [128 l][136 m-pairs]) | bn2[512] @104448 | an2[128] @106496 | tot 107008
__global__ __launch_bounds__(256, 2) void k_fused() {
    extern __shared__ char dsm[];
    const int SIMG0 = 34816, SIMG1 = 69632, BN2 = 104448, AN2 = 106496;
    float* bn2s = (float*)(dsm + BN2);
    float* an2s = (float*)(dsm + AN2);

    int t = threadIdx.x, stripe = blockIdx.x;
    int w = t >> 5, lane = t & 31;
    uint32_t sb = smem_u32(dsm);

    // persistent loads: text tile (32KB + pad), bn2 stripe (2KB), an2 (512B)
    {
        uint4* stq = (uint4*)dsm;
        const uint4* tq = (const uint4*)g_text16u;
        for (int f = t; f < 2048; f += 256)
            stq[(f >> 4) * 17 + (f & 15)] = tq[f];
        bn2s[t] = g_bn2[stripe * 512 + t];
        bn2s[t + 256] = g_bn2[stripe * 512 + 256 + t];
        if (t < 128) an2s[t] = g_an2[t];
    }

    // prologue: async-load chunk 0 into buf 0 (rows = l, 16 uint4 per row)
    {
        const uint4* gq = (const uint4*)g_img16u + (size_t)stripe * 64;
        #pragma unroll
        for (int r = 0; r < 8; r++) {
            int f = t + 256 * r;
            int row = f >> 4, q = f & 15;
            cp_async16(sb + SIMG0 + (uint32_t)(row * 17 + q) * 16u,
                       gq + (size_t)row * 16384 + q);
        }
        asm volatile("cp.async.commit_group;" ::: "memory");
    }

    float acc2[16][4];
    #pragma unroll
    for (int lt = 0; lt < 16; lt++)
        #pragma unroll
        for (int r = 0; r < 4; r++) acc2[lt][r] = 0.f;

    __syncthreads();
    float an2v0 = an2s[w * 16 + (lane >> 2)];
    float an2v1 = an2s[w * 16 + (lane >> 2) + 8];

    uint32_t a_addr = (uint32_t)(w * 16 + (lane & 15)) * 272u
                    + (uint32_t)((lane >> 4) * 16);
    uint32_t b_row = (uint32_t)(lane & 15) * 272u;
    uint32_t b_colbase = (uint32_t)((lane >> 4) * 16);

    #pragma unroll 1
    for (int c = 0; c < 4; c++) {
        if (c < 3) {
            uint32_t dst = sb + (((c + 1) & 1) ? SIMG1 : SIMG0);
            const uint4* gq = (const uint4*)g_img16u
                            + (size_t)stripe * 64 + (size_t)(c + 1) * 16;
            #pragma unroll
            for (int r = 0; r < 8; r++) {
                int f = t + 256 * r;
                int row = f >> 4, q = f & 15;
                cp_async16(dst + (uint32_t)(row * 17 + q) * 16u,
                           gq + (size_t)row * 16384 + q);
            }
            asm volatile("cp.async.commit_group;" ::: "memory");
            asm volatile("cp.async.wait_group 1;" ::: "memory");
        } else {
            asm volatile("cp.async.wait_group 0;" ::: "memory");
        }
        __syncthreads();
        uint32_t sbi = sb + ((c & 1) ? SIMG1 : SIMG0);

        #pragma unroll 1
        for (int s = 0; s < 8; s++) {
            uint32_t scol = (uint32_t)(s * 32) + b_colbase;

            // ---- GEMM1: D[16 sel-n x 16 m], K = l = 128 ----
            // B from [l][m] tile via ldsm4t (rows = K): pairs (r0,r1)/(r2,r3)
            float c1[2][4];
            #pragma unroll
            for (int j = 0; j < 2; j++)
                #pragma unroll
                for (int r = 0; r < 4; r++) c1[j][r] = 0.f;

            #pragma unroll
            for (int kk = 0; kk < 8; kk++) {
                uint32_t a[4], bfr[4];
                ldsm4(a, sb + a_addr + kk * 32u);
                ldsm4t(bfr, sbi + b_row + (uint32_t)(kk * 16) * 272u + scol);
                mma_bf16(c1[0], a, bfr[0], bfr[1]);
                mma_bf16(c1[1], a, bfr[2], bfr[3]);
            }

            // ---- epilogue: E in regs, repack as A frag for GEMM2 ----
            uint32_t a2[4];
            #pragma unroll
            for (int j = 0; j < 2; j++) {
                float2 bn = *(float2*)&bn2s[(c << 7) + s * 16 + j * 8 + 2 * (lane & 3)];
                float e0 = efun(c1[j][0], an2v0, bn.x);
                float e1 = efun(c1[j][1], an2v0, bn.y);
                float e2 = efun(c1[j][2], an2v1, bn.x);
                float e3 = efun(c1[j][3], an2v1, bn.y);
                a2[2 * j]     = pack_bf16(e0, e1);
                a2[2 * j + 1] = pack_bf16(e2, e3);
            }

            // ---- GEMM2: acc2[sel-n, l] += E[n, m16] . img[m16, l] ----
            // B from [l][m] tile via ldsm4 (rows = N=l): pairs (r0,r2)/(r1,r3)
            #pragma unroll
            for (int lb = 0; lb < 8; lb++) {
                uint32_t b2r[4];
                ldsm4(b2r, sbi + b_row + (uint32_t)(lb * 16) * 272u + scol);
                mma_bf16(acc2[2 * lb],     a2, b2r[0], b2r[2]);
                mma_bf16(acc2[2 * lb + 1], a2, b2r[1], b2r[3]);
            }
        }
        __syncthreads();
    }

    // store partials: g_part[stripe][sel-n][l]
    int nbase = w * 16 + (lane >> 2);
    #pragma unroll
    for (int lt = 0; lt < 16; lt++) {
        int l = lt * 8 + 2 * (lane & 3);
        size_t base = (size_t)stripe * 16384 + (size_t)nbase * 128 + l;
        *(float2*)&g_part[base] = make_float2(acc2[lt][0], acc2[lt][1]);
        *(float2*)&g_part[base + 8 * 128] = make_float2(acc2[lt][2], acc2[lt][3]);
    }
}

// ================= K2: deterministic reduction of partials =================
__global__ void k_reduce() {
    int id = blockIdx.x * 64 + threadIdx.x;   // id = sel-n*128 + l, 16384
    float s = 0.f;
    #pragma unroll 16
    for (int st = 0; st < 256; st++)
        s += g_part[(size_t)st * 16384 + id];
    g_alsel[id] = s;
}

// ================= K3a: t_line =================
__global__ void k_tline() {
    int f = blockIdx.x * 256 + threadIdx.x;   // f = l*64 + w
    int l = f >> 6, w = f & 63;
    g_tline[f] = 0.5f * (g_alsel[(2 * w) * 128 + l] + g_alsel[(2 * w + 1) * 128 + l]);
}

// ================= K3b: pre1 = b1 + W1a @ t_line =================
__global__ void k_pre1(const float* __restrict__ w1, const float* __restrict__ b1) {
    int f = blockIdx.x * 256 + threadIdx.x;   // f = b*4096 + o*64 + w
    int b = f >> 12, o = (f >> 6) & 63, w = f & 63;
    float s = __ldg(&b1[o]);
    #pragma unroll 8
    for (int c = 0; c < 64; c++)
        s = fmaf(__ldg(&w1[o * 128 + c]), g_tline[(b * 64 + c) * 64 + w], s);
    g_pre1[f] = s;
}

// ================= K4: per-voxel MLP + gated blend (fp16 mma) =================
#define SVB 272
#define SWB 144
__global__ __launch_bounds__(256, 2) void k_mlp(const float* __restrict__ img,
                                                const float* __restrict__ w1,
                                                const float* __restrict__ w2,
                                                const float* __restrict__ b2,
                                                float* __restrict__ out) {
    extern __shared__ char dsm[];
    const int X16 = 0, H16 = 17408, W1O = 34816, W2O = 44032;
    uint32_t sb = smem_u32(dsm);

    int t = threadIdx.x;
    int bb = blockIdx.x >> 10;
    int m0 = (blockIdx.x & 1023) << 7;
    int w = t >> 5, lane = t & 31;
    int obase = (w & 3) * 16;
    int vwbase = (w >> 2) * 64;

    for (int f = t; f < 2048; f += 256) {
        int c = f >> 5, v4 = f & 31;
        float4 xv = ((const float4*)(img + (size_t)(bb * 64 + c) * M_DIM + m0))[v4];
        *(uint2*)(dsm + X16 + c * SVB + v4 * 8) =
            make_uint2(pack_f16(xv.x, xv.y), pack_f16(xv.z, xv.w));
    }
    for (int f = t; f < 4096; f += 256) {
        int o = f >> 6, c = f & 63;
        *(uint16_t*)(dsm + W1O + o * SWB + c * 2) =
            __half_as_ushort(__float2half_rn(__ldg(&w1[o * 128 + 64 + c])));
        *(uint16_t*)(dsm + W2O + o * SWB + c * 2) =
            __half_as_ushort(__float2half_rn(__ldg(&w2[o * 64 + c])));
    }

    int orow = obase + (lane >> 2);
    int vcol = 2 * (lane & 3);
    const float* pr = g_pre1 + bb * 4096;
    float acc[8][4];
    #pragma unroll
    for (int j = 0; j < 8; j++) {
        int ws = (vwbase + 8 * j + vcol) & 63;
        acc[j][0] = pr[orow * 64 + ws];
        acc[j][1] = pr[orow * 64 + ws + 1];
        acc[j][2] = pr[(orow + 8) * 64 + ws];
        acc[j][3] = pr[(orow + 8) * 64 + ws + 1];
    }
    __syncthreads();

    uint32_t aw_addr = (uint32_t)(obase + (lane & 15)) * SWB + (uint32_t)((lane >> 4) * 16);
    uint32_t bx_row = (uint32_t)(lane & 15) * SVB;
    uint32_t bx_col = (uint32_t)(vwbase * 2 + (lane >> 4) * 16);

    #pragma unroll
    for (int k = 0; k < 4; k++) {
        uint32_t a[4];
        ldsm4(a, sb + W1O + aw_addr + k * 32u);
        #pragma unroll
        for (int q = 0; q < 4; q++) {
            uint32_t bx[4];
            ldsm4t(bx, sb + X16 + bx_row + (uint32_t)(16 * k) * SVB + bx_col + q * 32u);
            mma_f16(acc[2 * q],     a, bx[0], bx[1]);
            mma_f16(acc[2 * q + 1], a, bx[2], bx[3]);
        }
    }

    #pragma unroll
    for (int j = 0; j < 8; j++) {
        int vox0 = vwbase + 8 * j + vcol;
        *(uint32_t*)(dsm + H16 + orow * SVB + vox0 * 2) =
            pack_f16(fmaxf(acc[j][0], 0.f), fmaxf(acc[j][1], 0.f));
        *(uint32_t*)(dsm + H16 + (orow + 8) * SVB + vox0 * 2) =
            pack_f16(fmaxf(acc[j][2], 0.f), fmaxf(acc[j][3], 0.f));
    }
    __syncthreads();

    float bv0 = __ldg(&b2[orow]), bv1 = __ldg(&b2[orow + 8]);
    #pragma unroll
    for (int j = 0; j < 8; j++) {
        acc[j][0] = bv0; acc[j][1] = bv0;
        acc[j][2] = bv1; acc[j][3] = bv1;
    }
    #pragma unroll
    for (int k = 0; k < 4; k++) {
        uint32_t a[4];
        ldsm4(a, sb + W2O + aw_addr + k * 32u);
        #pragma unroll
        for (int q = 0; q < 4; q++) {
            uint32_t bh[4];
            ldsm4t(bh, sb + H16 + bx_row + (uint32_t)(16 * k) * SVB + bx_col + q * 32u);
            mma_f16(acc[2 * q],     a, bh[0], bh[1]);
            mma_f16(acc[2 * q + 1], a, bh[2], bh[3]);
        }
    }

    const float* tl = g_tline + bb * 4096;
    #pragma unroll
    for (int j = 0; j < 8; j++) {
        int vox0 = vwbase + 8 * j + vcol;
        int ws = vox0 & 63;
        #pragma unroll
        for (int half = 0; half < 2; half++) {
            int row = orow + 8 * half;
            size_t gidx = (size_t)(bb * 64 + row) * M_DIM + m0 + vox0;
            float2 xv = *(const float2*)(img + gidx);
            float2 tv = *(const float2*)(tl + row * 64 + ws);
            float g0 = fast_sigmoid(acc[j][2 * half]);
            float g1 = fast_sigmoid(acc[j][2 * half + 1]);
            float2 ov;
            ov.x = fmaf(g0, tv.x - xv.x, xv.x);
            ov.y = fmaf(g1, tv.y - xv.y, xv.y);
            *(float2*)(out + gidx) = ov;
        }
    }
}

// ================= launch =================
extern "C" void kernel_launch(void* const* d_in, const int* in_sizes, int n_in,
                              void* d_out, int out_size) {
    const float* text = (const float*)d_in[0];
    const float* img  = (const float*)d_in[1];
    const float* w1   = (const float*)d_in[2];
    const float* b1   = (const float*)d_in[3];
    const float* w2   = (const float*)d_in[4];
    const float* b2   = (const float*)d_in[5];
    float* out = (float*)d_out;

    cudaFuncSetAttribute(k_fused, cudaFuncAttributeMaxDynamicSharedMemorySize, 107008);
    cudaFuncSetAttribute(k_mlp,   cudaFuncAttributeMaxDynamicSharedMemorySize, 53248);

    k_prepass<<<257, 256>>>(img, text);
    k_fused  <<<256, 256, 107008>>>();
    k_reduce <<<256, 64>>>();
    k_tline  <<<32, 256>>>();
    k_pre1   <<<32, 256>>>(w1, b1);
    k_mlp    <<<2048, 256, 53248>>>(img, w1, w2, b2, out);
}

// round 8
// speedup vs baseline: 6.1047x; 1.1294x over previous
#include <cuda_runtime.h>
#include <cuda_bf16.h>
#include <cuda_fp16.h>
#include <math.h>
#include <stdint.h>

// ---------------- problem constants ----------------
#define L_DIM   128
#define N_DIM   256
#define M_DIM   131072
#define IMG_BSTRIDE 8388608   // 64*131072

// Only n in {4w+1, 4w+2} feed the output. sel s in [0,128): n = 4*(s>>1)+1+(s&1).

// ---------------- scratch (static device memory; no allocs) ----------------
__device__ float g_part[128 * 16384];          // alignedT partials [stripe][sel-n][l]
__device__ float g_tline[2 * 64 * 64];         // [b][c][w]  ([l][w], l = b*64+c)
__device__ float g_pre1[2 * 64 * 64];          // [b][o][w]

// ---------------- MUFU-based fast math ----------------
__device__ __forceinline__ float mufu_sigmoid(float x) {
    float e;
    asm("ex2.approx.f32 %0, %1;" : "=f"(e) : "f"(-1.4426950408889634f * x));
    float r;
    asm("rcp.approx.f32 %0, %1;" : "=f"(r) : "f"(1.0f + e));
    return r;
}
__device__ __forceinline__ float efun(float dot, float an, float bn) {
    float d2 = fmaxf(an + bn - 2.f * dot, 0.f);
    float c;
    asm("sqrt.approx.f32 %0, %1;" : "=f"(c) : "f"(d2));
    float e;
    asm("ex2.approx.f32 %0, %1;" : "=f"(e) : "f"(-0.14426950408889634f * c));
    return 1e-4f * e;
}

// ---------------- warp MMA helpers ----------------
__device__ __forceinline__ uint32_t smem_u32(const void* p) {
    uint32_t a;
    asm("{ .reg .u64 t; cvta.to.shared.u64 t, %1; cvt.u32.u64 %0, t; }" : "=r"(a) : "l"(p));
    return a;
}
__device__ __forceinline__ void ldsm4(uint32_t* r, uint32_t a) {
    asm volatile("ldmatrix.sync.aligned.m8n8.x4.shared.b16 {%0,%1,%2,%3}, [%4];"
                 : "=r"(r[0]), "=r"(r[1]), "=r"(r[2]), "=r"(r[3]) : "r"(a));
}
__device__ __forceinline__ void ldsm4t(uint32_t* r, uint32_t a) {
    asm volatile("ldmatrix.sync.aligned.m8n8.x4.trans.shared.b16 {%0,%1,%2,%3}, [%4];"
                 : "=r"(r[0]), "=r"(r[1]), "=r"(r[2]), "=r"(r[3]) : "r"(a));
}
__device__ __forceinline__ void mma_bf16(float* d, const uint32_t* a,
                                         uint32_t b0, uint32_t b1) {
    asm volatile("mma.sync.aligned.m16n8k16.row.col.f32.bf16.bf16.f32 "
                 "{%0,%1,%2,%3}, {%4,%5,%6,%7}, {%8,%9}, {%0,%1,%2,%3};"
                 : "+f"(d[0]), "+f"(d[1]), "+f"(d[2]), "+f"(d[3])
                 : "r"(a[0]), "r"(a[1]), "r"(a[2]), "r"(a[3]), "r"(b0), "r"(b1));
}
__device__ __forceinline__ void mma_f16(float* d, const uint32_t* a,
                                        uint32_t b0, uint32_t b1) {
    asm volatile("mma.sync.aligned.m16n8k16.row.col.f32.f16.f16.f32 "
                 "{%0,%1,%2,%3}, {%4,%5,%6,%7}, {%8,%9}, {%0,%1,%2,%3};"
                 : "+f"(d[0]), "+f"(d[1]), "+f"(d[2]), "+f"(d[3])
                 : "r"(a[0]), "r"(a[1]), "r"(a[2]), "r"(a[3]), "r"(b0), "r"(b1));
}
__device__ __forceinline__ uint32_t pack_bf16(float lo, float hi) {
    uint32_t r;
    asm("cvt.rn.bf16x2.f32 %0, %1, %2;" : "=r"(r) : "f"(hi), "f"(lo));
    return r;
}
__device__ __forceinline__ uint32_t pack_f16(float lo, float hi) {
    uint32_t r;
    asm("cvt.rn.f16x2.f32 %0, %1, %2;" : "=r"(r) : "f"(hi), "f"(lo));
    return r;
}
__device__ __forceinline__ void cp_async16(uint32_t daddr, const void* gptr) {
    asm volatile("cp.async.ca.shared.global [%0], [%1], 16;"
                 :: "r"(daddr), "l"(gptr) : "memory");
}
__device__ __forceinline__ float bf16_hl(uint32_t u, int hi) {
    uint16_t h = hi ? (uint16_t)(u >> 16) : (uint16_t)(u & 0xFFFF);
    return __bfloat162float(__ushort_as_bfloat16(h));
}

// ================= K1: fully-fused tensor-core pipeline ======================
// 128 CTAs x 256 thr, 1/SM. CTA = m-stripe of 1024 (8 chunks of 128 m).
// Per chunk: cp.async fp32 -> convert bf16 + bn2 -> GEMM1 -> E -> GEMM2.
// smem bytes: TEXT 128x272 @0 | STG0 fp32 128x528 @34816 | STG1 @102400 |
//   IMGB 128x272 @169984 | TMP f2[256] @204800 | BN2[128] @206848 |
//   AN2[128] @207360 | total 207872
__global__ __launch_bounds__(256, 1) void k_fused(const float* __restrict__ img,
                                                  const float* __restrict__ text) {
    extern __shared__ char dsm[];
    const int TEXT = 0, STG0 = 34816, STG1 = 102400, IMGB = 169984,
              TMP = 204800, BN2 = 206848, AN2 = 207360;
    float* bn2s = (float*)(dsm + BN2);
    float* an2s = (float*)(dsm + AN2);
    float2* tmpf = (float2*)(dsm + TMP);

    int t = threadIdx.x, bid = blockIdx.x;
    int w = t >> 5, lane = t & 31;
    uint32_t sb = smem_u32(dsm);
    uint32_t sbi = sb + IMGB;

    // ---- build text tile [sel-n s][l-pair c2] bf16, pitch 272B ----
    for (int p = t; p < 8192; p += 256) {
        int s = p >> 6, c2 = p & 63;
        int n = 4 * (s >> 1) + 1 + (s & 1);
        *(uint32_t*)(dsm + TEXT + s * 272 + c2 * 4) =
            pack_bf16(__ldg(&text[(2 * c2) * 256 + n]),
                      __ldg(&text[(2 * c2 + 1) * 256 + n]));
    }

    // prologue: async-load chunk 0 fp32 into STG0 (rows=l, 32 uint4/row, pad 33)
    {
        const char* gb = (const char*)(img + (size_t)bid * 1024);
        #pragma unroll
        for (int r = 0; r < 16; r++) {
            int f = t + 256 * r;
            int row = f >> 5, q = f & 31;
            cp_async16(sb + STG0 + (uint32_t)(row * 33 + q) * 16u,
                       gb + (size_t)row * 524288 + q * 16);
        }
        asm volatile("cp.async.commit_group;" ::: "memory");
    }
    __syncthreads();

    // ---- an2 from the bf16 text tile (consistent with GEMM quantization) ----
    if (t < 128) {
        float s = 0.f;
        #pragma unroll 8
        for (int c2 = 0; c2 < 64; c2++) {
            uint32_t u = *(uint32_t*)(dsm + TEXT + t * 272 + c2 * 4);
            float v0 = bf16_hl(u, 0), v1 = bf16_hl(u, 1);
            s = fmaf(v0, v0, fmaf(v1, v1, s));
        }
        an2s[t] = s;
    }

    float acc2[16][4];
    #pragma unroll
    for (int lt = 0; lt < 16; lt++)
        #pragma unroll
        for (int r = 0; r < 4; r++) acc2[lt][r] = 0.f;

    __syncthreads();
    float an2v0 = an2s[w * 16 + (lane >> 2)];
    float an2v1 = an2s[w * 16 + (lane >> 2) + 8];

    uint32_t a_addr = (uint32_t)(w * 16 + (lane & 15)) * 272u
                    + (uint32_t)((lane >> 4) * 16);
    uint32_t b_row = (uint32_t)(lane & 31 & 15) * 272u;
    b_row = (uint32_t)(lane & 15) * 272u;
    uint32_t b_colbase = (uint32_t)((lane >> 4) * 16);

    int cvt_c2 = t & 63;          // this thread's fixed l-pair column
    int cvt_q0 = t >> 6;          // row phase

    #pragma unroll 1
    for (int c = 0; c < 8; c++) {
        // issue next chunk fp32 into the other stage buffer
        if (c < 7) {
            uint32_t dst = sb + (((c + 1) & 1) ? STG1 : STG0);
            const char* gb = (const char*)(img + (size_t)bid * 1024 + (c + 1) * 128);
            #pragma unroll
            for (int r = 0; r < 16; r++) {
                int f = t + 256 * r;
                int row = f >> 5, q = f & 31;
                cp_async16(dst + (uint32_t)(row * 33 + q) * 16u,
                           gb + (size_t)row * 524288 + q * 16);
            }
            asm volatile("cp.async.commit_group;" ::: "memory");
            asm volatile("cp.async.wait_group 1;" ::: "memory");
        } else {
            asm volatile("cp.async.wait_group 0;" ::: "memory");
        }
        __syncthreads();   // stage(c) visible; IMGB free (prev mma done)

        // ---- convert fp32 stage -> bf16 IMGB tile [l][m-pair], + bn2 ----
        {
            const char* stg = dsm + ((c & 1) ? STG1 : STG0);
            float s0 = 0.f, s1 = 0.f;
            #pragma unroll 8
            for (int i = 0; i < 32; i++) {
                int row = cvt_q0 + 4 * i;
                float2 v = *(const float2*)(stg + row * 528 + cvt_c2 * 8);
                s0 = fmaf(v.x, v.x, s0);
                s1 = fmaf(v.y, v.y, s1);
                *(uint32_t*)(dsm + IMGB + row * 272 + cvt_c2 * 4) = pack_bf16(v.x, v.y);
            }
            tmpf[t] = make_float2(s0, s1);
        }
        __syncthreads();
        if (t < 128) {
            int c2i = t & 63, bsel = t >> 6;
            float v = 0.f;
            #pragma unroll
            for (int q = 0; q < 4; q++) {
                float2 p2 = tmpf[q * 64 + c2i];
                v += bsel ? p2.y : p2.x;
            }
            bn2s[2 * c2i + bsel] = v;
        }
        __syncthreads();   // IMGB + bn2 ready

        #pragma unroll 1
        for (int s = 0; s < 8; s++) {
            uint32_t scol = (uint32_t)(s * 32) + b_colbase;

            // ---- GEMM1: D[16 sel-n x 16 m], K=l=128; B via ldsm4t ----
            float c1[2][4];
            #pragma unroll
            for (int j = 0; j < 2; j++)
                #pragma unroll
                for (int r = 0; r < 4; r++) c1[j][r] = 0.f;

            #pragma unroll
            for (int kk = 0; kk < 8; kk++) {
                uint32_t a[4], bfr[4];
                ldsm4(a, sb + TEXT + a_addr + kk * 32u);
                ldsm4t(bfr, sbi + b_row + (uint32_t)(kk * 16) * 272u + scol);
                mma_bf16(c1[0], a, bfr[0], bfr[1]);
                mma_bf16(c1[1], a, bfr[2], bfr[3]);
            }

            // ---- epilogue: E in regs, repack as A frag for GEMM2 ----
            uint32_t a2[4];
            #pragma unroll
            for (int j = 0; j < 2; j++) {
                float2 bn = *(float2*)&bn2s[s * 16 + j * 8 + 2 * (lane & 3)];
                float e0 = efun(c1[j][0], an2v0, bn.x);
                float e1 = efun(c1[j][1], an2v0, bn.y);
                float e2 = efun(c1[j][2], an2v1, bn.x);
                float e3 = efun(c1[j][3], an2v1, bn.y);
                a2[2 * j]     = pack_bf16(e0, e1);
                a2[2 * j + 1] = pack_bf16(e2, e3);
            }

            // ---- GEMM2: acc2[sel-n, l] += E . img; B via ldsm4 ----
            #pragma unroll
            for (int lb = 0; lb < 8; lb++) {
                uint32_t b2r[4];
                ldsm4(b2r, sbi + b_row + (uint32_t)(lb * 16) * 272u + scol);
                mma_bf16(acc2[2 * lb],     a2, b2r[0], b2r[2]);
                mma_bf16(acc2[2 * lb + 1], a2, b2r[1], b2r[3]);
            }
        }
        __syncthreads();   // done reading IMGB before next convert
    }

    // store partials: g_part[bid][sel-n][l]
    int nbase = w * 16 + (lane >> 2);
    #pragma unroll
    for (int lt = 0; lt < 16; lt++) {
        int l = lt * 8 + 2 * (lane & 3);
        size_t base = (size_t)bid * 16384 + (size_t)nbase * 128 + l;
        *(float2*)&g_part[base] = make_float2(acc2[lt][0], acc2[lt][1]);
        *(float2*)&g_part[base + 8 * 128] = make_float2(acc2[lt][2], acc2[lt][3]);
    }
}

// ================= K2: reduce partials + interp -> t_line ====================
__global__ void k_redtl() {
    int f = blockIdx.x * 256 + threadIdx.x;   // 8192: w = f>>7, l = f&127
    int w = f >> 7, l = f & 127;
    float a = 0.f, b = 0.f;
    #pragma unroll 8
    for (int st = 0; st < 128; st++) {
        a += g_part[(size_t)st * 16384 + (2 * w) * 128 + l];
        b += g_part[(size_t)st * 16384 + (2 * w + 1) * 128 + l];
    }
    g_tline[l * 64 + w] = 0.5f * (a + b);
}

// ================= K3: pre1 = b1 + W1a @ t_line =================
__global__ void k_pre1(const float* __restrict__ w1, const float* __restrict__ b1) {
    int f = blockIdx.x * 256 + threadIdx.x;   // f = b*4096 + o*64 + w
    int b = f >> 12, o = (f >> 6) & 63, w = f & 63;
    float s = __ldg(&b1[o]);
    #pragma unroll 8
    for (int c = 0; c < 64; c++)
        s = fmaf(__ldg(&w1[o * 128 + c]), g_tline[(b * 64 + c) * 64 + w], s);
    g_pre1[f] = s;
}

// ================= K4: per-voxel MLP + gated blend (fp16 mma) =================
#define SVB 272
#define SWB 144
__global__ __launch_bounds__(256, 2) void k_mlp(const float* __restrict__ img,
                                                const float* __restrict__ w1,
                                                const float* __restrict__ w2,
                                                const float* __restrict__ b2,
                                                float* __restrict__ out) {
    extern __shared__ char dsm[];
    const int X16 = 0, H16 = 17408, W1O = 34816, W2O = 44032;
    uint32_t sb = smem_u32(dsm);

    int t = threadIdx.x;
    int bb = blockIdx.x >> 10;
    int m0 = (blockIdx.x & 1023) << 7;
    int w = t >> 5, lane = t & 31;
    int obase = (w & 3) * 16;
    int vwbase = (w >> 2) * 64;

    for (int f = t; f < 2048; f += 256) {
        int c = f >> 5, v4 = f & 31;
        float4 xv = ((const float4*)(img + (size_t)(bb * 64 + c) * M_DIM + m0))[v4];
        *(uint2*)(dsm + X16 + c * SVB + v4 * 8) =
            make_uint2(pack_f16(xv.x, xv.y), pack_f16(xv.z, xv.w));
    }
    for (int f = t; f < 4096; f += 256) {
        int o = f >> 6, c = f & 63;
        *(uint16_t*)(dsm + W1O + o * SWB + c * 2) =
            __half_as_ushort(__float2half_rn(__ldg(&w1[o * 128 + 64 + c])));
        *(uint16_t*)(dsm + W2O + o * SWB + c * 2) =
            __half_as_ushort(__float2half_rn(__ldg(&w2[o * 64 + c])));
    }

    int orow = obase + (lane >> 2);
    int vcol = 2 * (lane & 3);
    const float* pr = g_pre1 + bb * 4096;
    float acc[8][4];
    #pragma unroll
    for (int j = 0; j < 8; j++) {
        int ws = (vwbase + 8 * j + vcol) & 63;
        acc[j][0] = pr[orow * 64 + ws];
        acc[j][1] = pr[orow * 64 + ws + 1];
        acc[j][2] = pr[(orow + 8) * 64 + ws];
        acc[j][3] = pr[(orow + 8) * 64 + ws + 1];
    }
    __syncthreads();

    uint32_t aw_addr = (uint32_t)(obase + (lane & 15)) * SWB + (uint32_t)((lane >> 4) * 16);
    uint32_t bx_row = (uint32_t)(lane & 15) * SVB;
    uint32_t bx_col = (uint32_t)(vwbase * 2 + (lane >> 4) * 16);

    #pragma unroll
    for (int k = 0; k < 4; k++) {
        uint32_t a[4];
        ldsm4(a, sb + W1O + aw_addr + k * 32u);
        #pragma unroll
        for (int q = 0; q < 4; q++) {
            uint32_t bx[4];
            ldsm4t(bx, sb + X16 + bx_row + (uint32_t)(16 * k) * SVB + bx_col + q * 32u);
            mma_f16(acc[2 * q],     a, bx[0], bx[1]);
            mma_f16(acc[2 * q + 1], a, bx[2], bx[3]);
        }
    }

    #pragma unroll
    for (int j = 0; j < 8; j++) {
        int vox0 = vwbase + 8 * j + vcol;
        *(uint32_t*)(dsm + H16 + orow * SVB + vox0 * 2) =
            pack_f16(fmaxf(acc[j][0], 0.f), fmaxf(acc[j][1], 0.f));
        *(uint32_t*)(dsm + H16 + (orow + 8) * SVB + vox0 * 2) =
            pack_f16(fmaxf(acc[j][2], 0.f), fmaxf(acc[j][3], 0.f));
    }
    __syncthreads();

    float bv0 = __ldg(&b2[orow]), bv1 = __ldg(&b2[orow + 8]);
    #pragma unroll
    for (int j = 0; j < 8; j++) {
        acc[j][0] = bv0; acc[j][1] = bv0;
        acc[j][2] = bv1; acc[j][3] = bv1;
    }
    #pragma unroll
    for (int k = 0; k < 4; k++) {
        uint32_t a[4];
        ldsm4(a, sb + W2O + aw_addr + k * 32u);
        #pragma unroll
        for (int q = 0; q < 4; q++) {
            uint32_t bh[4];
            ldsm4t(bh, sb + H16 + bx_row + (uint32_t)(16 * k) * SVB + bx_col + q * 32u);
            mma_f16(acc[2 * q],     a, bh[0], bh[1]);
            mma_f16(acc[2 * q + 1], a, bh[2], bh[3]);
        }
    }

    const float* tl = g_tline + bb * 4096;
    #pragma unroll
    for (int j = 0; j < 8; j++) {
        int vox0 = vwbase + 8 * j + vcol;
        int ws = vox0 & 63;
        #pragma unroll
        for (int half = 0; half < 2; half++) {
            int row = orow + 8 * half;
            size_t gidx = (size_t)(bb * 64 + row) * M_DIM + m0 + vox0;
            float2 xv = *(const float2*)(img + gidx);
            float2 tv = *(const float2*)(tl + row * 64 + ws);
            float g0 = mufu_sigmoid(acc[j][2 * half]);
            float g1 = mufu_sigmoid(acc[j][2 * half + 1]);
            float2 ov;
            ov.x = fmaf(g0, tv.x - xv.x, xv.x);
            ov.y = fmaf(g1, tv.y - xv.y, xv.y);
            *(float2*)(out + gidx) = ov;
        }
    }
}

// ================= launch =================
extern "C" void kernel_launch(void* const* d_in, const int* in_sizes, int n_in,
                              void* d_out, int out_size) {
    const float* text = (const float*)d_in[0];
    const float* img  = (const float*)d_in[1];
    const float* w1   = (const float*)d_in[2];
    const float* b1   = (const float*)d_in[3];
    const float* w2   = (const float*)d_in[4];
    const float* b2   = (const float*)d_in[5];
    float* out = (float*)d_out;

    cudaFuncSetAttribute(k_fused, cudaFuncAttributeMaxDynamicSharedMemorySize, 207872);
    cudaFuncSetAttribute(k_mlp,   cudaFuncAttributeMaxDynamicSharedMemorySize, 53248);

    k_fused<<<128, 256, 207872>>>(img, text);
    k_redtl<<<32, 256>>>();
    k_pre1 <<<32, 256>>>(w1, b1);
    k_mlp  <<<2048, 256, 53248>>>(img, w1, w2, b2, out);
}

// round 9
// speedup vs baseline: 7.2443x; 1.1867x over previous
#include <cuda_runtime.h>
#include <cuda_bf16.h>
#include <cuda_fp16.h>
#include <math.h>
#include <stdint.h>

// ---------------- problem constants ----------------
#define L_DIM   128
#define N_DIM   256
#define M_DIM   131072
#define IMG_BSTRIDE 8388608   // 64*131072

// Only n in {4w+1, 4w+2} feed the output. sel s in [0,128): n = 4*(s>>1)+1+(s&1).

// ---------------- scratch (static device memory; no allocs) ----------------
__device__ float g_part[128 * 16384];          // alignedT partials [stripe][sel-n][l]
__device__ float g_tline[2 * 64 * 64];         // [b][c][w]  ([l][w], l = b*64+c)
__device__ float g_pre1[2 * 64 * 64];          // [b][o][w]

// ---------------- MUFU-based fast math ----------------
__device__ __forceinline__ float mufu_sigmoid(float x) {
    float e;
    asm("ex2.approx.f32 %0, %1;" : "=f"(e) : "f"(-1.4426950408889634f * x));
    float r;
    asm("rcp.approx.f32 %0, %1;" : "=f"(r) : "f"(1.0f + e));
    return r;
}
__device__ __forceinline__ float efun(float dot, float an, float bn) {
    float d2 = fmaxf(an + bn - 2.f * dot, 0.f);
    float c;
    asm("sqrt.approx.f32 %0, %1;" : "=f"(c) : "f"(d2));
    float e;
    asm("ex2.approx.f32 %0, %1;" : "=f"(e) : "f"(-0.14426950408889634f * c));
    return 1e-4f * e;
}

// ---------------- warp MMA helpers ----------------
__device__ __forceinline__ uint32_t smem_u32(const void* p) {
    uint32_t a;
    asm("{ .reg .u64 t; cvta.to.shared.u64 t, %1; cvt.u32.u64 %0, t; }" : "=r"(a) : "l"(p));
    return a;
}
__device__ __forceinline__ void ldsm4(uint32_t* r, uint32_t a) {
    asm volatile("ldmatrix.sync.aligned.m8n8.x4.shared.b16 {%0,%1,%2,%3}, [%4];"
                 : "=r"(r[0]), "=r"(r[1]), "=r"(r[2]), "=r"(r[3]) : "r"(a));
}
__device__ __forceinline__ void ldsm4t(uint32_t* r, uint32_t a) {
    asm volatile("ldmatrix.sync.aligned.m8n8.x4.trans.shared.b16 {%0,%1,%2,%3}, [%4];"
                 : "=r"(r[0]), "=r"(r[1]), "=r"(r[2]), "=r"(r[3]) : "r"(a));
}
__device__ __forceinline__ void mma_bf16(float* d, const uint32_t* a,
                                         uint32_t b0, uint32_t b1) {
    asm volatile("mma.sync.aligned.m16n8k16.row.col.f32.bf16.bf16.f32 "
                 "{%0,%1,%2,%3}, {%4,%5,%6,%7}, {%8,%9}, {%0,%1,%2,%3};"
                 : "+f"(d[0]), "+f"(d[1]), "+f"(d[2]), "+f"(d[3])
                 : "r"(a[0]), "r"(a[1]), "r"(a[2]), "r"(a[3]), "r"(b0), "r"(b1));
}
__device__ __forceinline__ void mma_f16(float* d, const uint32_t* a,
                                        uint32_t b0, uint32_t b1) {
    asm volatile("mma.sync.aligned.m16n8k16.row.col.f32.f16.f16.f32 "
                 "{%0,%1,%2,%3}, {%4,%5,%6,%7}, {%8,%9}, {%0,%1,%2,%3};"
                 : "+f"(d[0]), "+f"(d[1]), "+f"(d[2]), "+f"(d[3])
                 : "r"(a[0]), "r"(a[1]), "r"(a[2]), "r"(a[3]), "r"(b0), "r"(b1));
}
__device__ __forceinline__ uint32_t pack_bf16(float lo, float hi) {
    uint32_t r;
    asm("cvt.rn.bf16x2.f32 %0, %1, %2;" : "=r"(r) : "f"(hi), "f"(lo));
    return r;
}
__device__ __forceinline__ uint32_t pack_f16(float lo, float hi) {
    uint32_t r;
    asm("cvt.rn.f16x2.f32 %0, %1, %2;" : "=r"(r) : "f"(hi), "f"(lo));
    return r;
}
__device__ __forceinline__ void cp_async16(uint32_t daddr, const void* gptr) {
    asm volatile("cp.async.ca.shared.global [%0], [%1], 16;"
                 :: "r"(daddr), "l"(gptr) : "memory");
}
__device__ __forceinline__ float bf16_hl(uint32_t u, int hi) {
    uint16_t h = hi ? (uint16_t)(u >> 16) : (uint16_t)(u & 0xFFFF);
    return __bfloat162float(__ushort_as_bfloat16(h));
}

// ================= K1: fully-fused tensor-core pipeline ======================
// 128 CTAs x 256 thr, 1/SM. CTA = m-stripe of 1024 (8 chunks of 128 m).
// Text A-fragments hoisted into registers (invariant across chunks/s-iters).
__global__ __launch_bounds__(256, 1) void k_fused(const float* __restrict__ img,
                                                  const float* __restrict__ text) {
    extern __shared__ char dsm[];
    const int TEXT = 0, STG0 = 34816, STG1 = 102400, IMGB = 169984,
              TMP = 204800, BN2 = 206848, AN2 = 207360;
    float* bn2s = (float*)(dsm + BN2);
    float* an2s = (float*)(dsm + AN2);
    float2* tmpf = (float2*)(dsm + TMP);

    int t = threadIdx.x, bid = blockIdx.x;
    int w = t >> 5, lane = t & 31;
    uint32_t sb = smem_u32(dsm);
    uint32_t sbi = sb + IMGB;

    // ---- build text tile [sel-n s][l-pair c2] bf16, pitch 272B ----
    for (int p = t; p < 8192; p += 256) {
        int s = p >> 6, c2 = p & 63;
        int n = 4 * (s >> 1) + 1 + (s & 1);
        *(uint32_t*)(dsm + TEXT + s * 272 + c2 * 4) =
            pack_bf16(__ldg(&text[(2 * c2) * 256 + n]),
                      __ldg(&text[(2 * c2 + 1) * 256 + n]));
    }

    // prologue: async-load chunk 0 fp32 into STG0 (rows=l, 32 uint4/row, pad 33)
    {
        const char* gb = (const char*)(img + (size_t)bid * 1024);
        #pragma unroll
        for (int r = 0; r < 16; r++) {
            int f = t + 256 * r;
            int row = f >> 5, q = f & 31;
            cp_async16(sb + STG0 + (uint32_t)(row * 33 + q) * 16u,
                       gb + (size_t)row * 524288 + q * 16);
        }
        asm volatile("cp.async.commit_group;" ::: "memory");
    }
    __syncthreads();

    // ---- an2 from the bf16 text tile ----
    if (t < 128) {
        float s = 0.f;
        #pragma unroll 8
        for (int c2 = 0; c2 < 64; c2++) {
            uint32_t u = *(uint32_t*)(dsm + TEXT + t * 272 + c2 * 4);
            float v0 = bf16_hl(u, 0), v1 = bf16_hl(u, 1);
            s = fmaf(v0, v0, fmaf(v1, v1, s));
        }
        an2s[t] = s;
    }
    __syncthreads();

    // ---- hoist text A fragments (invariant) into registers ----
    uint32_t a_addr = (uint32_t)(w * 16 + (lane & 15)) * 272u
                    + (uint32_t)((lane >> 4) * 16);
    uint32_t atex[8][4];
    #pragma unroll
    for (int kk = 0; kk < 8; kk++)
        ldsm4(atex[kk], sb + TEXT + a_addr + kk * 32u);

    float acc2[16][4];
    #pragma unroll
    for (int lt = 0; lt < 16; lt++)
        #pragma unroll
        for (int r = 0; r < 4; r++) acc2[lt][r] = 0.f;

    float an2v0 = an2s[w * 16 + (lane >> 2)];
    float an2v1 = an2s[w * 16 + (lane >> 2) + 8];

    uint32_t b_row = (uint32_t)(lane & 15) * 272u;
    uint32_t b_colbase = (uint32_t)((lane >> 4) * 16);

    int cvt_c2 = t & 63;          // this thread's fixed l-pair column
    int cvt_q0 = t >> 6;          // row phase

    #pragma unroll 1
    for (int c = 0; c < 8; c++) {
        if (c < 7) {
            uint32_t dst = sb + (((c + 1) & 1) ? STG1 : STG0);
            const char* gb = (const char*)(img + (size_t)bid * 1024 + (c + 1) * 128);
            #pragma unroll
            for (int r = 0; r < 16; r++) {
                int f = t + 256 * r;
                int row = f >> 5, q = f & 31;
                cp_async16(dst + (uint32_t)(row * 33 + q) * 16u,
                           gb + (size_t)row * 524288 + q * 16);
            }
            asm volatile("cp.async.commit_group;" ::: "memory");
            asm volatile("cp.async.wait_group 1;" ::: "memory");
        } else {
            asm volatile("cp.async.wait_group 0;" ::: "memory");
        }
        __syncthreads();   // stage(c) visible; IMGB free (prev mma done)

        // ---- convert fp32 stage -> bf16 IMGB tile [l][m-pair], + bn2 ----
        {
            const char* stg = dsm + ((c & 1) ? STG1 : STG0);
            float s0 = 0.f, s1 = 0.f;
            #pragma unroll 8
            for (int i = 0; i < 32; i++) {
                int row = cvt_q0 + 4 * i;
                float2 v = *(const float2*)(stg + row * 528 + cvt_c2 * 8);
                s0 = fmaf(v.x, v.x, s0);
                s1 = fmaf(v.y, v.y, s1);
                *(uint32_t*)(dsm + IMGB + row * 272 + cvt_c2 * 4) = pack_bf16(v.x, v.y);
            }
            tmpf[t] = make_float2(s0, s1);
        }
        __syncthreads();
        if (t < 128) {
            int c2i = t & 63, bsel = t >> 6;
            float v = 0.f;
            #pragma unroll
            for (int q = 0; q < 4; q++) {
                float2 p2 = tmpf[q * 64 + c2i];
                v += bsel ? p2.y : p2.x;
            }
            bn2s[2 * c2i + bsel] = v;
        }
        __syncthreads();   // IMGB + bn2 ready

        #pragma unroll 1
        for (int s = 0; s < 8; s++) {
            uint32_t scol = (uint32_t)(s * 32) + b_colbase;

            // ---- GEMM1: D[16 sel-n x 16 m], K=l=128; B via ldsm4t ----
            float c1[2][4];
            #pragma unroll
            for (int j = 0; j < 2; j++)
                #pragma unroll
                for (int r = 0; r < 4; r++) c1[j][r] = 0.f;

            #pragma unroll
            for (int kk = 0; kk < 8; kk++) {
                uint32_t bfr[4];
                ldsm4t(bfr, sbi + b_row + (uint32_t)(kk * 16) * 272u + scol);
                mma_bf16(c1[0], atex[kk], bfr[0], bfr[1]);
                mma_bf16(c1[1], atex[kk], bfr[2], bfr[3]);
            }

            // ---- epilogue: E in regs, repack as A frag for GEMM2 ----
            uint32_t a2[4];
            #pragma unroll
            for (int j = 0; j < 2; j++) {
                float2 bn = *(float2*)&bn2s[s * 16 + j * 8 + 2 * (lane & 3)];
                float e0 = efun(c1[j][0], an2v0, bn.x);
                float e1 = efun(c1[j][1], an2v0, bn.y);
                float e2 = efun(c1[j][2], an2v1, bn.x);
                float e3 = efun(c1[j][3], an2v1, bn.y);
                a2[2 * j]     = pack_bf16(e0, e1);
                a2[2 * j + 1] = pack_bf16(e2, e3);
            }

            // ---- GEMM2: acc2[sel-n, l] += E . img; B via ldsm4 ----
            #pragma unroll
            for (int lb = 0; lb < 8; lb++) {
                uint32_t b2r[4];
                ldsm4(b2r, sbi + b_row + (uint32_t)(lb * 16) * 272u + scol);
                mma_bf16(acc2[2 * lb],     a2, b2r[0], b2r[2]);
                mma_bf16(acc2[2 * lb + 1], a2, b2r[1], b2r[3]);
            }
        }
        __syncthreads();   // done reading IMGB before next convert
    }

    // store partials: g_part[bid][sel-n][l]
    int nbase = w * 16 + (lane >> 2);
    #pragma unroll
    for (int lt = 0; lt < 16; lt++) {
        int l = lt * 8 + 2 * (lane & 3);
        size_t base = (size_t)bid * 16384 + (size_t)nbase * 128 + l;
        *(float2*)&g_part[base] = make_float2(acc2[lt][0], acc2[lt][1]);
        *(float2*)&g_part[base + 8 * 128] = make_float2(acc2[lt][2], acc2[lt][3]);
    }
}

// ================= K2: reduce partials + interp -> t_line ====================
__global__ void k_redtl() {
    int f = blockIdx.x * 256 + threadIdx.x;   // 8192: w = f>>7, l = f&127
    int w = f >> 7, l = f & 127;
    float a = 0.f, b = 0.f;
    #pragma unroll 8
    for (int st = 0; st < 128; st++) {
        a += g_part[(size_t)st * 16384 + (2 * w) * 128 + l];
        b += g_part[(size_t)st * 16384 + (2 * w + 1) * 128 + l];
    }
    g_tline[l * 64 + w] = 0.5f * (a + b);
}

// ================= K3: pre1 = b1 + W1a @ t_line =================
__global__ void k_pre1(const float* __restrict__ w1, const float* __restrict__ b1) {
    int f = blockIdx.x * 256 + threadIdx.x;   // f = b*4096 + o*64 + w
    int b = f >> 12, o = (f >> 6) & 63, w = f & 63;
    float s = __ldg(&b1[o]);
    #pragma unroll 8
    for (int c = 0; c < 64; c++)
        s = fmaf(__ldg(&w1[o * 128 + c]), g_tline[(b * 64 + c) * 64 + w], s);
    g_pre1[f] = s;
}

// ================= K4: per-voxel MLP + gated blend (fp16 mma) =================
// 2048 blocks x 512 thr (16 warps); 128 voxels/block; warp = 16 o x 32 vox.
// acc = 16 regs -> <=64 regs/thread -> 2 blocks/SM = 50% occupancy.
#define SVB 272
#define SWB 144
__global__ __launch_bounds__(512, 2) void k_mlp(const float* __restrict__ img,
                                                const float* __restrict__ w1,
                                                const float* __restrict__ w2,
                                                const float* __restrict__ b2,
                                                float* __restrict__ out) {
    extern __shared__ char dsm[];
    const int X16 = 0, H16 = 17408, W1O = 34816, W2O = 44032;
    uint32_t sb = smem_u32(dsm);

    int t = threadIdx.x;
    int bb = blockIdx.x >> 10;
    int m0 = (blockIdx.x & 1023) << 7;
    int w = t >> 5, lane = t & 31;
    int obase = (w & 3) * 16;
    int vwbase = (w >> 2) * 32;

    for (int f = t; f < 2048; f += 512) {
        int c = f >> 5, v4 = f & 31;
        float4 xv = ((const float4*)(img + (size_t)(bb * 64 + c) * M_DIM + m0))[v4];
        *(uint2*)(dsm + X16 + c * SVB + v4 * 8) =
            make_uint2(pack_f16(xv.x, xv.y), pack_f16(xv.z, xv.w));
    }
    for (int f = t; f < 4096; f += 512) {
        int o = f >> 6, c = f & 63;
        *(uint16_t*)(dsm + W1O + o * SWB + c * 2) =
            __half_as_ushort(__float2half_rn(__ldg(&w1[o * 128 + 64 + c])));
        *(uint16_t*)(dsm + W2O + o * SWB + c * 2) =
            __half_as_ushort(__float2half_rn(__ldg(&w2[o * 64 + c])));
    }

    int orow = obase + (lane >> 2);
    int vcol = 2 * (lane & 3);
    const float* pr = g_pre1 + bb * 4096;
    float acc[4][4];
    #pragma unroll
    for (int j = 0; j < 4; j++) {
        int ws = (vwbase + 8 * j + vcol) & 63;
        acc[j][0] = pr[orow * 64 + ws];
        acc[j][1] = pr[orow * 64 + ws + 1];
        acc[j][2] = pr[(orow + 8) * 64 + ws];
        acc[j][3] = pr[(orow + 8) * 64 + ws + 1];
    }
    __syncthreads();

    uint32_t aw_addr = (uint32_t)(obase + (lane & 15)) * SWB + (uint32_t)((lane >> 4) * 16);
    uint32_t bx_row = (uint32_t)(lane & 15) * SVB;
    uint32_t bx_col = (uint32_t)(vwbase * 2 + (lane >> 4) * 16);

    // ---- layer 1: h = pre1 + W1b @ x ----
    #pragma unroll
    for (int k = 0; k < 4; k++) {
        uint32_t a[4];
        ldsm4(a, sb + W1O + aw_addr + k * 32u);
        #pragma unroll
        for (int q = 0; q < 2; q++) {
            uint32_t bx[4];
            ldsm4t(bx, sb + X16 + bx_row + (uint32_t)(16 * k) * SVB + bx_col + q * 32u);
            mma_f16(acc[2 * q],     a, bx[0], bx[1]);
            mma_f16(acc[2 * q + 1], a, bx[2], bx[3]);
        }
    }

    // ---- relu -> fp16 H smem ----
    #pragma unroll
    for (int j = 0; j < 4; j++) {
        int vox0 = vwbase + 8 * j + vcol;
        *(uint32_t*)(dsm + H16 + orow * SVB + vox0 * 2) =
            pack_f16(fmaxf(acc[j][0], 0.f), fmaxf(acc[j][1], 0.f));
        *(uint32_t*)(dsm + H16 + (orow + 8) * SVB + vox0 * 2) =
            pack_f16(fmaxf(acc[j][2], 0.f), fmaxf(acc[j][3], 0.f));
    }
    __syncthreads();

    // ---- layer 2: g = b2 + W2 @ H ----
    float bv0 = __ldg(&b2[orow]), bv1 = __ldg(&b2[orow + 8]);
    #pragma unroll
    for (int j = 0; j < 4; j++) {
        acc[j][0] = bv0; acc[j][1] = bv0;
        acc[j][2] = bv1; acc[j][3] = bv1;
    }
    #pragma unroll
    for (int k = 0; k < 4; k++) {
        uint32_t a[4];
        ldsm4(a, sb + W2O + aw_addr + k * 32u);
        #pragma unroll
        for (int q = 0; q < 2; q++) {
            uint32_t bh[4];
            ldsm4t(bh, sb + H16 + bx_row + (uint32_t)(16 * k) * SVB + bx_col + q * 32u);
            mma_f16(acc[2 * q],     a, bh[0], bh[1]);
            mma_f16(acc[2 * q + 1], a, bh[2], bh[3]);
        }
    }

    // ---- gate + blend + store ----
    const float* tl = g_tline + bb * 4096;
    #pragma unroll
    for (int j = 0; j < 4; j++) {
        int vox0 = vwbase + 8 * j + vcol;
        int ws = vox0 & 63;
        #pragma unroll
        for (int half = 0; half < 2; half++) {
            int row = orow + 8 * half;
            size_t gidx = (size_t)(bb * 64 + row) * M_DIM + m0 + vox0;
            float2 xv = *(const float2*)(img + gidx);
            float2 tv = *(const float2*)(tl + row * 64 + ws);
            float g0 = mufu_sigmoid(acc[j][2 * half]);
            float g1 = mufu_sigmoid(acc[j][2 * half + 1]);
            float2 ov;
            ov.x = fmaf(g0, tv.x - xv.x, xv.x);
            ov.y = fmaf(g1, tv.y - xv.y, xv.y);
            *(float2*)(out + gidx) = ov;
        }
    }
}

// ================= launch =================
extern "C" void kernel_launch(void* const* d_in, const int* in_sizes, int n_in,
                              void* d_out, int out_size) {
    const float* text = (const float*)d_in[0];
    const float* img  = (const float*)d_in[1];
    const float* w1   = (const float*)d_in[2];
    const float* b1   = (const float*)d_in[3];
    const float* w2   = (const float*)d_in[4];
    const float* b2   = (const float*)d_in[5];
    float* out = (float*)d_out;

    cudaFuncSetAttribute(k_fused, cudaFuncAttributeMaxDynamicSharedMemorySize, 207872);
    cudaFuncSetAttribute(k_mlp,   cudaFuncAttributeMaxDynamicSharedMemorySize, 53248);

    k_fused<<<128, 256, 207872>>>(img, text);
    k_redtl<<<32, 256>>>();
    k_pre1 <<<32, 256>>>(w1, b1);
    k_mlp  <<<2048, 512, 53248>>>(img, w1, w2, b2, out);
}

// round 10
// speedup vs baseline: 7.6225x; 1.0522x over previous
#include <cuda_runtime.h>
#include <cuda_bf16.h>
#include <cuda_fp16.h>
#include <math.h>
#include <stdint.h>

// ---------------- problem constants ----------------
#define L_DIM   128
#define N_DIM   256
#define M_DIM   131072
#define IMG_BSTRIDE 8388608   // 64*131072

// Only n in {4w+1, 4w+2} feed the output. sel s in [0,128): n = 4*(s>>1)+1+(s&1).

// ---------------- scratch (static device memory; no allocs) ----------------
__device__ float g_part[128 * 16384];          // alignedT partials [stripe][sel-n][l]
__device__ float g_tline[2 * 64 * 64];         // [b][c][w]  ([l][w], l = b*64+c)
__device__ float g_pre1[2 * 64 * 64];          // [b][o][w]

// ---------------- MUFU-based fast math ----------------
__device__ __forceinline__ float mufu_sigmoid(float x) {
    float e;
    asm("ex2.approx.f32 %0, %1;" : "=f"(e) : "f"(-1.4426950408889634f * x));
    float r;
    asm("rcp.approx.f32 %0, %1;" : "=f"(r) : "f"(1.0f + e));
    return r;
}
__device__ __forceinline__ float efun(float dot, float an, float bn) {
    float d2 = fmaxf(an + bn - 2.f * dot, 0.f);
    float c;
    asm("sqrt.approx.f32 %0, %1;" : "=f"(c) : "f"(d2));
    float e;
    asm("ex2.approx.f32 %0, %1;" : "=f"(e) : "f"(-0.14426950408889634f * c));
    return 1e-4f * e;
}

// ---------------- warp MMA helpers ----------------
__device__ __forceinline__ uint32_t smem_u32(const void* p) {
    uint32_t a;
    asm("{ .reg .u64 t; cvta.to.shared.u64 t, %1; cvt.u32.u64 %0, t; }" : "=r"(a) : "l"(p));
    return a;
}
__device__ __forceinline__ void ldsm4(uint32_t* r, uint32_t a) {
    asm volatile("ldmatrix.sync.aligned.m8n8.x4.shared.b16 {%0,%1,%2,%3}, [%4];"
                 : "=r"(r[0]), "=r"(r[1]), "=r"(r[2]), "=r"(r[3]) : "r"(a));
}
__device__ __forceinline__ void ldsm4t(uint32_t* r, uint32_t a) {
    asm volatile("ldmatrix.sync.aligned.m8n8.x4.trans.shared.b16 {%0,%1,%2,%3}, [%4];"
                 : "=r"(r[0]), "=r"(r[1]), "=r"(r[2]), "=r"(r[3]) : "r"(a));
}
__device__ __forceinline__ void mma_bf16(float* d, const uint32_t* a,
                                         uint32_t b0, uint32_t b1) {
    asm volatile("mma.sync.aligned.m16n8k16.row.col.f32.bf16.bf16.f32 "
                 "{%0,%1,%2,%3}, {%4,%5,%6,%7}, {%8,%9}, {%0,%1,%2,%3};"
                 : "+f"(d[0]), "+f"(d[1]), "+f"(d[2]), "+f"(d[3])
                 : "r"(a[0]), "r"(a[1]), "r"(a[2]), "r"(a[3]), "r"(b0), "r"(b1));
}
__device__ __forceinline__ void mma_f16(float* d, const uint32_t* a,
                                        uint32_t b0, uint32_t b1) {
    asm volatile("mma.sync.aligned.m16n8k16.row.col.f32.f16.f16.f32 "
                 "{%0,%1,%2,%3}, {%4,%5,%6,%7}, {%8,%9}, {%0,%1,%2,%3};"
                 : "+f"(d[0]), "+f"(d[1]), "+f"(d[2]), "+f"(d[3])
                 : "r"(a[0]), "r"(a[1]), "r"(a[2]), "r"(a[3]), "r"(b0), "r"(b1));
}
__device__ __forceinline__ uint32_t pack_bf16(float lo, float hi) {
    uint32_t r;
    asm("cvt.rn.bf16x2.f32 %0, %1, %2;" : "=r"(r) : "f"(hi), "f"(lo));
    return r;
}
__device__ __forceinline__ uint32_t pack_f16(float lo, float hi) {
    uint32_t r;
    asm("cvt.rn.f16x2.f32 %0, %1, %2;" : "=r"(r) : "f"(hi), "f"(lo));
    return r;
}
__device__ __forceinline__ void cp_async16(uint32_t daddr, const void* gptr) {
    asm volatile("cp.async.ca.shared.global [%0], [%1], 16;"
                 :: "r"(daddr), "l"(gptr) : "memory");
}
__device__ __forceinline__ float bf16_hl(uint32_t u, int hi) {
    uint16_t h = hi ? (uint16_t)(u >> 16) : (uint16_t)(u & 0xFFFF);
    return __bfloat162float(__ushort_as_bfloat16(h));
}

// ================= K1: fully-fused tensor-core pipeline ======================
// 128 CTAs x 256 thr, 1/SM. CTA = m-stripe of 1024 (8 chunks of 128 m).
// smem: TEXT 34816 | STG0 @34816 (67584) | STG1 @102400 | IMGB @169984 (34816)
//   | TMP @204800 (4096) | BN2 @208896 | AN2 @209408 | total 209920
__global__ __launch_bounds__(256, 1) void k_fused(const float* __restrict__ img,
                                                  const float* __restrict__ text) {
    extern __shared__ char dsm[];
    const int TEXT = 0, STG0 = 34816, STG1 = 102400, IMGB = 169984,
              TMP = 204800, BN2 = 208896, AN2 = 209408;
    float* bn2s = (float*)(dsm + BN2);
    float* an2s = (float*)(dsm + AN2);

    int t = threadIdx.x, bid = blockIdx.x;
    int w = t >> 5, lane = t & 31;
    uint32_t sb = smem_u32(dsm);
    uint32_t sbi = sb + IMGB;

    // ---- build text tile [sel-n s][l-pair c2] bf16, pitch 272B ----
    for (int p = t; p < 8192; p += 256) {
        int s = p >> 6, c2 = p & 63;
        int n = 4 * (s >> 1) + 1 + (s & 1);
        *(uint32_t*)(dsm + TEXT + s * 272 + c2 * 4) =
            pack_bf16(__ldg(&text[(2 * c2) * 256 + n]),
                      __ldg(&text[(2 * c2 + 1) * 256 + n]));
    }

    // prologue: async-load chunk 0 fp32 into STG0 (rows=l, 32 uint4/row, pad 33)
    {
        const char* gb = (const char*)(img + (size_t)bid * 1024);
        #pragma unroll
        for (int r = 0; r < 16; r++) {
            int f = t + 256 * r;
            int row = f >> 5, q = f & 31;
            cp_async16(sb + STG0 + (uint32_t)(row * 33 + q) * 16u,
                       gb + (size_t)row * 524288 + q * 16);
        }
        asm volatile("cp.async.commit_group;" ::: "memory");
    }
    __syncthreads();

    // ---- an2 from the bf16 text tile ----
    if (t < 128) {
        float s = 0.f;
        #pragma unroll 8
        for (int c2 = 0; c2 < 64; c2++) {
            uint32_t u = *(uint32_t*)(dsm + TEXT + t * 272 + c2 * 4);
            float v0 = bf16_hl(u, 0), v1 = bf16_hl(u, 1);
            s = fmaf(v0, v0, fmaf(v1, v1, s));
        }
        an2s[t] = s;
    }
    __syncthreads();

    // ---- hoist text A fragments (invariant) into registers ----
    uint32_t a_addr = (uint32_t)(w * 16 + (lane & 15)) * 272u
                    + (uint32_t)((lane >> 4) * 16);
    uint32_t atex[8][4];
    #pragma unroll
    for (int kk = 0; kk < 8; kk++)
        ldsm4(atex[kk], sb + TEXT + a_addr + kk * 32u);

    float acc2[16][4];
    #pragma unroll
    for (int lt = 0; lt < 16; lt++)
        #pragma unroll
        for (int r = 0; r < 4; r++) acc2[lt][r] = 0.f;

    float an2v0 = an2s[w * 16 + (lane >> 2)];
    float an2v1 = an2s[w * 16 + (lane >> 2) + 8];

    uint32_t b_row = (uint32_t)(lane & 15) * 272u;
    uint32_t b_colbase = (uint32_t)((lane >> 4) * 16);

    int c4 = t & 31;              // this thread's float4 column in convert
    int rp = t >> 5;              // row phase

    #pragma unroll 1
    for (int c = 0; c < 8; c++) {
        if (c < 7) {
            uint32_t dst = sb + (((c + 1) & 1) ? STG1 : STG0);
            const char* gb = (const char*)(img + (size_t)bid * 1024 + (c + 1) * 128);
            #pragma unroll
            for (int r = 0; r < 16; r++) {
                int f = t + 256 * r;
                int row = f >> 5, q = f & 31;
                cp_async16(dst + (uint32_t)(row * 33 + q) * 16u,
                           gb + (size_t)row * 524288 + q * 16);
            }
            asm volatile("cp.async.commit_group;" ::: "memory");
            asm volatile("cp.async.wait_group 1;" ::: "memory");
        } else {
            asm volatile("cp.async.wait_group 0;" ::: "memory");
        }
        __syncthreads();   // stage(c) visible; IMGB free (prev mma done)

        // ---- convert fp32 stage -> bf16 IMGB tile [l][m-pair], + bn2 (wide) --
        {
            const char* stg = dsm + ((c & 1) ? STG1 : STG0);
            float s0 = 0.f, s1 = 0.f, s2 = 0.f, s3 = 0.f;
            #pragma unroll 8
            for (int i = 0; i < 16; i++) {
                int row = rp + 8 * i;
                float4 v = *(const float4*)(stg + row * 528 + c4 * 16);
                s0 = fmaf(v.x, v.x, s0);
                s1 = fmaf(v.y, v.y, s1);
                s2 = fmaf(v.z, v.z, s2);
                s3 = fmaf(v.w, v.w, s3);
                *(uint2*)(dsm + IMGB + row * 272 + c4 * 8) =
                    make_uint2(pack_bf16(v.x, v.y), pack_bf16(v.z, v.w));
            }
            ((float4*)(dsm + TMP))[t] = make_float4(s0, s1, s2, s3);
        }
        __syncthreads();
        if (t < 128) {
            float v = 0.f;
            #pragma unroll
            for (int q = 0; q < 8; q++)
                v += ((const float*)(dsm + TMP))[(q * 32 + (t >> 2)) * 4 + (t & 3)];
            bn2s[t] = v;
        }
        __syncthreads();   // IMGB + bn2 ready

        #pragma unroll 1
        for (int s = 0; s < 8; s++) {
            uint32_t scol = (uint32_t)(s * 32) + b_colbase;

            // ---- GEMM1: D[16 sel-n x 16 m], K=l=128; B via ldsm4t ----
            float c1[2][4];
            #pragma unroll
            for (int j = 0; j < 2; j++)
                #pragma unroll
                for (int r = 0; r < 4; r++) c1[j][r] = 0.f;

            #pragma unroll
            for (int kk = 0; kk < 8; kk++) {
                uint32_t bfr[4];
                ldsm4t(bfr, sbi + b_row + (uint32_t)(kk * 16) * 272u + scol);
                mma_bf16(c1[0], atex[kk], bfr[0], bfr[1]);
                mma_bf16(c1[1], atex[kk], bfr[2], bfr[3]);
            }

            // ---- epilogue: E in regs, repack as A frag for GEMM2 ----
            uint32_t a2[4];
            #pragma unroll
            for (int j = 0; j < 2; j++) {
                float2 bn = *(float2*)&bn2s[s * 16 + j * 8 + 2 * (lane & 3)];
                float e0 = efun(c1[j][0], an2v0, bn.x);
                float e1 = efun(c1[j][1], an2v0, bn.y);
                float e2 = efun(c1[j][2], an2v1, bn.x);
                float e3 = efun(c1[j][3], an2v1, bn.y);
                a2[2 * j]     = pack_bf16(e0, e1);
                a2[2 * j + 1] = pack_bf16(e2, e3);
            }

            // ---- GEMM2: acc2[sel-n, l] += E . img; B via ldsm4 ----
            #pragma unroll
            for (int lb = 0; lb < 8; lb++) {
                uint32_t b2r[4];
                ldsm4(b2r, sbi + b_row + (uint32_t)(lb * 16) * 272u + scol);
                mma_bf16(acc2[2 * lb],     a2, b2r[0], b2r[2]);
                mma_bf16(acc2[2 * lb + 1], a2, b2r[1], b2r[3]);
            }
        }
        __syncthreads();   // done reading IMGB before next convert
    }

    // store partials: g_part[bid][sel-n][l]
    int nbase = w * 16 + (lane >> 2);
    #pragma unroll
    for (int lt = 0; lt < 16; lt++) {
        int l = lt * 8 + 2 * (lane & 3);
        size_t base = (size_t)bid * 16384 + (size_t)nbase * 128 + l;
        *(float2*)&g_part[base] = make_float2(acc2[lt][0], acc2[lt][1]);
        *(float2*)&g_part[base + 8 * 128] = make_float2(acc2[lt][2], acc2[lt][3]);
    }
}

// ================= K2: reduce partials + interp -> t_line ====================
__global__ void k_redtl() {
    int f = blockIdx.x * 256 + threadIdx.x;   // 8192: w = f>>7, l = f&127
    int w = f >> 7, l = f & 127;
    float a = 0.f, b = 0.f;
    #pragma unroll 8
    for (int st = 0; st < 128; st++) {
        a += g_part[(size_t)st * 16384 + (2 * w) * 128 + l];
        b += g_part[(size_t)st * 16384 + (2 * w + 1) * 128 + l];
    }
    g_tline[l * 64 + w] = 0.5f * (a + b);
}

// ================= K3: pre1 = b1 + W1a @ t_line =================
__global__ void k_pre1(const float* __restrict__ w1, const float* __restrict__ b1) {
    int f = blockIdx.x * 256 + threadIdx.x;   // f = b*4096 + o*64 + w
    int b = f >> 12, o = (f >> 6) & 63, w = f & 63;
    float s = __ldg(&b1[o]);
    #pragma unroll 8
    for (int c = 0; c < 64; c++)
        s = fmaf(__ldg(&w1[o * 128 + c]), g_tline[(b * 64 + c) * 64 + w], s);
    g_pre1[f] = s;
}

// ================= K4: per-voxel MLP + gated blend (fp16 mma) =================
// 1024 blocks x 512 thr; 256 voxels/block (two sequential 128-vox tiles).
// Weights/pre1/tline staged to smem ONCE per block via wide coalesced loads.
// smem: X16@0 (17408) | H16@17408 | W1@34816 (9216) | W2@44032 (9216) |
//       PRE@53248 (64x272=17408) | TL@70656 (17408) | total 88064
#define SVB 272
#define SWB 144
__global__ __launch_bounds__(512, 2) void k_mlp(const float* __restrict__ img,
                                                const float* __restrict__ w1,
                                                const float* __restrict__ w2,
                                                const float* __restrict__ b2,
                                                float* __restrict__ out) {
    extern __shared__ char dsm[];
    const int X16 = 0, H16 = 17408, W1O = 34816, W2O = 44032,
              PRE = 53248, TL = 70656;
    uint32_t sb = smem_u32(dsm);

    int t = threadIdx.x;
    int bb = blockIdx.x >> 9;
    int m0 = (blockIdx.x & 511) << 8;
    int w = t >> 5, lane = t & 31;
    int obase = (w & 3) * 16;
    int vwbase = (w >> 2) * 32;

    // ---- stage weights (fp16), pre1, tline (fp32) once per block ----
    for (int f = t; f < 2048; f += 512) {
        int o = f >> 5, c2 = f & 31;
        float2 a = *(const float2*)&w1[o * 128 + 64 + 2 * c2];
        *(uint32_t*)(dsm + W1O + o * SWB + c2 * 4) = pack_f16(a.x, a.y);
        float2 b = *(const float2*)&w2[o * 64 + 2 * c2];
        *(uint32_t*)(dsm + W2O + o * SWB + c2 * 4) = pack_f16(b.x, b.y);
    }
    for (int f = t; f < 1024; f += 512) {
        int o = f >> 4, w4 = f & 15;
        *(float4*)(dsm + PRE + o * 272 + w4 * 16) =
            *(const float4*)&g_pre1[bb * 4096 + o * 64 + w4 * 4];
        *(float4*)(dsm + TL + o * 272 + w4 * 16) =
            *(const float4*)&g_tline[bb * 4096 + o * 64 + w4 * 4];
    }

    int orow = obase + (lane >> 2);
    int vcol = 2 * (lane & 3);
    float bv0 = __ldg(&b2[orow]), bv1 = __ldg(&b2[orow + 8]);

    uint32_t aw_addr = (uint32_t)(obase + (lane & 15)) * SWB + (uint32_t)((lane >> 4) * 16);
    uint32_t bx_row = (uint32_t)(lane & 15) * SVB;
    uint32_t bx_col = (uint32_t)(vwbase * 2 + (lane >> 4) * 16);

    #pragma unroll 1
    for (int tile = 0; tile < 2; tile++) {
        int m0t = m0 + tile * 128;

        // ---- load x tile -> fp16 smem (wide) ----
        for (int f = t; f < 1024; f += 512) {
            int cc = f >> 3, v8 = f & 7;
            const float4* gp = (const float4*)(img + (size_t)(bb * 64 + cc) * M_DIM + m0t)
                             + v8 * 4;
            float4 x0 = gp[0], x1 = gp[1], x2 = gp[2], x3 = gp[3];
            *(uint4*)(dsm + X16 + cc * SVB + v8 * 32) =
                make_uint4(pack_f16(x0.x, x0.y), pack_f16(x0.z, x0.w),
                           pack_f16(x1.x, x1.y), pack_f16(x1.z, x1.w));
            *(uint4*)(dsm + X16 + cc * SVB + v8 * 32 + 16) =
                make_uint4(pack_f16(x2.x, x2.y), pack_f16(x2.z, x2.w),
                           pack_f16(x3.x, x3.y), pack_f16(x3.z, x3.w));
        }
        __syncthreads();   // X ready; also protects prior tile's H reads

        // ---- acc init from PRE smem ----
        float acc[4][4];
        #pragma unroll
        for (int j = 0; j < 4; j++) {
            int ws = (vwbase + 8 * j + vcol) & 63;
            float2 p0 = *(const float2*)(dsm + PRE + orow * 272 + ws * 4);
            float2 p1 = *(const float2*)(dsm + PRE + (orow + 8) * 272 + ws * 4);
            acc[j][0] = p0.x; acc[j][1] = p0.y;
            acc[j][2] = p1.x; acc[j][3] = p1.y;
        }

        // ---- layer 1: h = pre1 + W1b @ x ----
        #pragma unroll
        for (int k = 0; k < 4; k++) {
            uint32_t a[4];
            ldsm4(a, sb + W1O + aw_addr + k * 32u);
            #pragma unroll
            for (int q = 0; q < 2; q++) {
                uint32_t bx[4];
                ldsm4t(bx, sb + X16 + bx_row + (uint32_t)(16 * k) * SVB + bx_col + q * 32u);
                mma_f16(acc[2 * q],     a, bx[0], bx[1]);
                mma_f16(acc[2 * q + 1], a, bx[2], bx[3]);
            }
        }

        // ---- relu -> fp16 H smem ----
        #pragma unroll
        for (int j = 0; j < 4; j++) {
            int vox0 = vwbase + 8 * j + vcol;
            *(uint32_t*)(dsm + H16 + orow * SVB + vox0 * 2) =
                pack_f16(fmaxf(acc[j][0], 0.f), fmaxf(acc[j][1], 0.f));
            *(uint32_t*)(dsm + H16 + (orow + 8) * SVB + vox0 * 2) =
                pack_f16(fmaxf(acc[j][2], 0.f), fmaxf(acc[j][3], 0.f));
        }
        __syncthreads();

        // ---- layer 2: g = b2 + W2 @ H ----
        #pragma unroll
        for (int j = 0; j < 4; j++) {
            acc[j][0] = bv0; acc[j][1] = bv0;
            acc[j][2] = bv1; acc[j][3] = bv1;
        }
        #pragma unroll
        for (int k = 0; k < 4; k++) {
            uint32_t a[4];
            ldsm4(a, sb + W2O + aw_addr + k * 32u);
            #pragma unroll
            for (int q = 0; q < 2; q++) {
                uint32_t bh[4];
                ldsm4t(bh, sb + H16 + bx_row + (uint32_t)(16 * k) * SVB + bx_col + q * 32u);
                mma_f16(acc[2 * q],     a, bh[0], bh[1]);
                mma_f16(acc[2 * q + 1], a, bh[2], bh[3]);
            }
        }

        // ---- gate + blend + store ----
        #pragma unroll
        for (int j = 0; j < 4; j++) {
            int vox0 = vwbase + 8 * j + vcol;
            int ws = vox0 & 63;
            #pragma unroll
            for (int half = 0; half < 2; half++) {
                int row = orow + 8 * half;
                size_t gidx = (size_t)(bb * 64 + row) * M_DIM + m0t + vox0;
                float2 xv = *(const float2*)(img + gidx);
                float2 tv = *(const float2*)(dsm + TL + row * 272 + ws * 4);
                float g0 = mufu_sigmoid(acc[j][2 * half]);
                float g1 = mufu_sigmoid(acc[j][2 * half + 1]);
                float2 ov;
                ov.x = fmaf(g0, tv.x - xv.x, xv.x);
                ov.y = fmaf(g1, tv.y - xv.y, xv.y);
                *(float2*)(out + gidx) = ov;
            }
        }
    }
}

// ================= launch =================
extern "C" void kernel_launch(void* const* d_in, const int* in_sizes, int n_in,
                              void* d_out, int out_size) {
    const float* text = (const float*)d_in[0];
    const float* img  = (const float*)d_in[1];
    const float* w1   = (const float*)d_in[2];
    const float* b1   = (const float*)d_in[3];
    const float* w2   = (const float*)d_in[4];
    const float* b2   = (const float*)d_in[5];
    float* out = (float*)d_out;

    cudaFuncSetAttribute(k_fused, cudaFuncAttributeMaxDynamicSharedMemorySize, 209920);
    cudaFuncSetAttribute(k_mlp,   cudaFuncAttributeMaxDynamicSharedMemorySize, 88064);

    k_fused<<<128, 256, 209920>>>(img, text);
    k_redtl<<<32, 256>>>();
    k_pre1 <<<32, 256>>>(w1, b1);
    k_mlp  <<<1024, 512, 88064>>>(img, w1, w2, b2, out);
}

// round 11
// speedup vs baseline: 8.1207x; 1.0654x over previous
#include <cuda_runtime.h>
#include <cuda_bf16.h>
#include <cuda_fp16.h>
#include <math.h>
#include <stdint.h>

// ---------------- problem constants ----------------
#define L_DIM   128
#define N_DIM   256
#define M_DIM   131072
#define IMG_BSTRIDE 8388608   // 64*131072

// Only n in {4w+1, 4w+2} feed the output. sel s in [0,128): n = 4*(s>>1)+1+(s&1).

// ---------------- scratch (static device memory; no allocs) ----------------
__device__ float g_part[128 * 16384];          // alignedT partials [stripe][sel-n][l]
__device__ float g_tline[2 * 64 * 64];         // [b][c][w]  ([l][w], l = b*64+c)
__device__ float g_pre1[2 * 64 * 64];          // [b][o][w]

// ---------------- MUFU-based fast math ----------------
__device__ __forceinline__ float mufu_sigmoid(float x) {
    float e;
    asm("ex2.approx.f32 %0, %1;" : "=f"(e) : "f"(-1.4426950408889634f * x));
    float r;
    asm("rcp.approx.f32 %0, %1;" : "=f"(r) : "f"(1.0f + e));
    return r;
}
__device__ __forceinline__ float efun(float dot, float an, float bn) {
    float d2 = fmaxf(an + bn - 2.f * dot, 0.f);
    float c;
    asm("sqrt.approx.f32 %0, %1;" : "=f"(c) : "f"(d2));
    float e;
    asm("ex2.approx.f32 %0, %1;" : "=f"(e) : "f"(-0.14426950408889634f * c));
    return 1e-4f * e;
}

// ---------------- warp MMA helpers ----------------
__device__ __forceinline__ uint32_t smem_u32(const void* p) {
    uint32_t a;
    asm("{ .reg .u64 t; cvta.to.shared.u64 t, %1; cvt.u32.u64 %0, t; }" : "=r"(a) : "l"(p));
    return a;
}
__device__ __forceinline__ void ldsm4(uint32_t* r, uint32_t a) {
    asm volatile("ldmatrix.sync.aligned.m8n8.x4.shared.b16 {%0,%1,%2,%3}, [%4];"
                 : "=r"(r[0]), "=r"(r[1]), "=r"(r[2]), "=r"(r[3]) : "r"(a));
}
__device__ __forceinline__ void ldsm4t(uint32_t* r, uint32_t a) {
    asm volatile("ldmatrix.sync.aligned.m8n8.x4.trans.shared.b16 {%0,%1,%2,%3}, [%4];"
                 : "=r"(r[0]), "=r"(r[1]), "=r"(r[2]), "=r"(r[3]) : "r"(a));
}
__device__ __forceinline__ uint32_t movm(uint32_t a) {
    uint32_t d;
    asm volatile("movmatrix.sync.aligned.m8n8.trans.b16 %0, %1;" : "=r"(d) : "r"(a));
    return d;
}
__device__ __forceinline__ void mma_bf16(float* d, const uint32_t* a,
                                         uint32_t b0, uint32_t b1) {
    asm volatile("mma.sync.aligned.m16n8k16.row.col.f32.bf16.bf16.f32 "
                 "{%0,%1,%2,%3}, {%4,%5,%6,%7}, {%8,%9}, {%0,%1,%2,%3};"
                 : "+f"(d[0]), "+f"(d[1]), "+f"(d[2]), "+f"(d[3])
                 : "r"(a[0]), "r"(a[1]), "r"(a[2]), "r"(a[3]), "r"(b0), "r"(b1));
}
__device__ __forceinline__ void mma_f16(float* d, const uint32_t* a,
                                        uint32_t b0, uint32_t b1) {
    asm volatile("mma.sync.aligned.m16n8k16.row.col.f32.f16.f16.f32 "
                 "{%0,%1,%2,%3}, {%4,%5,%6,%7}, {%8,%9}, {%0,%1,%2,%3};"
                 : "+f"(d[0]), "+f"(d[1]), "+f"(d[2]), "+f"(d[3])
                 : "r"(a[0]), "r"(a[1]), "r"(a[2]), "r"(a[3]), "r"(b0), "r"(b1));
}
__device__ __forceinline__ uint32_t pack_bf16(float lo, float hi) {
    uint32_t r;
    asm("cvt.rn.bf16x2.f32 %0, %1, %2;" : "=r"(r) : "f"(hi), "f"(lo));
    return r;
}
__device__ __forceinline__ uint32_t pack_f16(float lo, float hi) {
    uint32_t r;
    asm("cvt.rn.f16x2.f32 %0, %1, %2;" : "=r"(r) : "f"(hi), "f"(lo));
    return r;
}
__device__ __forceinline__ void cp_async16(uint32_t daddr, const void* gptr) {
    asm volatile("cp.async.ca.shared.global [%0], [%1], 16;"
                 :: "r"(daddr), "l"(gptr) : "memory");
}
__device__ __forceinline__ float bf16_hl(uint32_t u, int hi) {
    uint16_t h = hi ? (uint16_t)(u >> 16) : (uint16_t)(u & 0xFFFF);
    return __bfloat162float(__ushort_as_bfloat16(h));
}

// ================= K1: fully-fused tensor-core pipeline ======================
// 128 CTAs x 256 thr, 1/SM. CTA = m-stripe of 1024 (8 chunks of 128 m).
// GEMM1 B-frags saved; GEMM2 B-frags derived via movmatrix (no re-ldsm).
__global__ __launch_bounds__(256, 1) void k_fused(const float* __restrict__ img,
                                                  const float* __restrict__ text) {
    extern __shared__ char dsm[];
    const int TEXT = 0, STG0 = 34816, STG1 = 102400, IMGB = 169984,
              TMP = 204800, BN2 = 208896, AN2 = 209408;
    float* bn2s = (float*)(dsm + BN2);
    float* an2s = (float*)(dsm + AN2);

    int t = threadIdx.x, bid = blockIdx.x;
    int w = t >> 5, lane = t & 31;
    uint32_t sb = smem_u32(dsm);
    uint32_t sbi = sb + IMGB;

    // ---- build text tile [sel-n s][l-pair c2] bf16, pitch 272B ----
    for (int p = t; p < 8192; p += 256) {
        int s = p >> 6, c2 = p & 63;
        int n = 4 * (s >> 1) + 1 + (s & 1);
        *(uint32_t*)(dsm + TEXT + s * 272 + c2 * 4) =
            pack_bf16(__ldg(&text[(2 * c2) * 256 + n]),
                      __ldg(&text[(2 * c2 + 1) * 256 + n]));
    }

    // prologue: async-load chunk 0 fp32 into STG0 (rows=l, 32 uint4/row, pad 33)
    {
        const char* gb = (const char*)(img + (size_t)bid * 1024);
        #pragma unroll
        for (int r = 0; r < 16; r++) {
            int f = t + 256 * r;
            int row = f >> 5, q = f & 31;
            cp_async16(sb + STG0 + (uint32_t)(row * 33 + q) * 16u,
                       gb + (size_t)row * 524288 + q * 16);
        }
        asm volatile("cp.async.commit_group;" ::: "memory");
    }
    __syncthreads();

    // ---- an2 from the bf16 text tile ----
    if (t < 128) {
        float s = 0.f;
        #pragma unroll 8
        for (int c2 = 0; c2 < 64; c2++) {
            uint32_t u = *(uint32_t*)(dsm + TEXT + t * 272 + c2 * 4);
            float v0 = bf16_hl(u, 0), v1 = bf16_hl(u, 1);
            s = fmaf(v0, v0, fmaf(v1, v1, s));
        }
        an2s[t] = s;
    }
    __syncthreads();

    // ---- hoist text A fragments (invariant) into registers ----
    uint32_t a_addr = (uint32_t)(w * 16 + (lane & 15)) * 272u
                    + (uint32_t)((lane >> 4) * 16);
    uint32_t atex[8][4];
    #pragma unroll
    for (int kk = 0; kk < 8; kk++)
        ldsm4(atex[kk], sb + TEXT + a_addr + kk * 32u);

    float acc2[16][4];
    #pragma unroll
    for (int lt = 0; lt < 16; lt++)
        #pragma unroll
        for (int r = 0; r < 4; r++) acc2[lt][r] = 0.f;

    float an2v0 = an2s[w * 16 + (lane >> 2)];
    float an2v1 = an2s[w * 16 + (lane >> 2) + 8];

    uint32_t b_row = (uint32_t)(lane & 15) * 272u;
    uint32_t b_colbase = (uint32_t)((lane >> 4) * 16);

    int c4 = t & 31;              // this thread's float4 column in convert
    int rp = t >> 5;              // row phase

    #pragma unroll 1
    for (int c = 0; c < 8; c++) {
        if (c < 7) {
            uint32_t dst = sb + (((c + 1) & 1) ? STG1 : STG0);
            const char* gb = (const char*)(img + (size_t)bid * 1024 + (c + 1) * 128);
            #pragma unroll
            for (int r = 0; r < 16; r++) {
                int f = t + 256 * r;
                int row = f >> 5, q = f & 31;
                cp_async16(dst + (uint32_t)(row * 33 + q) * 16u,
                           gb + (size_t)row * 524288 + q * 16);
            }
            asm volatile("cp.async.commit_group;" ::: "memory");
            asm volatile("cp.async.wait_group 1;" ::: "memory");
        } else {
            asm volatile("cp.async.wait_group 0;" ::: "memory");
        }
        __syncthreads();   // stage(c) visible; IMGB free (prev mma done)

        // ---- convert fp32 stage -> bf16 IMGB tile [l][m-pair], + bn2 (wide) --
        {
            const char* stg = dsm + ((c & 1) ? STG1 : STG0);
            float s0 = 0.f, s1 = 0.f, s2 = 0.f, s3 = 0.f;
            #pragma unroll 8
            for (int i = 0; i < 16; i++) {
                int row = rp + 8 * i;
                float4 v = *(const float4*)(stg + row * 528 + c4 * 16);
                s0 = fmaf(v.x, v.x, s0);
                s1 = fmaf(v.y, v.y, s1);
                s2 = fmaf(v.z, v.z, s2);
                s3 = fmaf(v.w, v.w, s3);
                *(uint2*)(dsm + IMGB + row * 272 + c4 * 8) =
                    make_uint2(pack_bf16(v.x, v.y), pack_bf16(v.z, v.w));
            }
            ((float4*)(dsm + TMP))[t] = make_float4(s0, s1, s2, s3);
        }
        __syncthreads();
        if (t < 128) {
            float v = 0.f;
            #pragma unroll
            for (int q = 0; q < 8; q++)
                v += ((const float*)(dsm + TMP))[(q * 32 + (t >> 2)) * 4 + (t & 3)];
            bn2s[t] = v;
        }
        __syncthreads();   // IMGB + bn2 ready

        #pragma unroll 1
        for (int s = 0; s < 8; s++) {
            uint32_t scol = (uint32_t)(s * 32) + b_colbase;

            // ---- GEMM1: D[16 sel-n x 16 m], K=l=128; B via ldsm4t, SAVED ----
            float c1[2][4];
            #pragma unroll
            for (int j = 0; j < 2; j++)
                #pragma unroll
                for (int r = 0; r < 4; r++) c1[j][r] = 0.f;

            uint32_t bsave[8][4];
            #pragma unroll
            for (int kk = 0; kk < 8; kk++) {
                ldsm4t(bsave[kk], sbi + b_row + (uint32_t)(kk * 16) * 272u + scol);
                mma_bf16(c1[0], atex[kk], bsave[kk][0], bsave[kk][1]);
                mma_bf16(c1[1], atex[kk], bsave[kk][2], bsave[kk][3]);
            }

            // ---- epilogue: E in regs, repack as A frag for GEMM2 ----
            uint32_t a2[4];
            #pragma unroll
            for (int j = 0; j < 2; j++) {
                float2 bn = *(float2*)&bn2s[s * 16 + j * 8 + 2 * (lane & 3)];
                float e0 = efun(c1[j][0], an2v0, bn.x);
                float e1 = efun(c1[j][1], an2v0, bn.y);
                float e2 = efun(c1[j][2], an2v1, bn.x);
                float e3 = efun(c1[j][3], an2v1, bn.y);
                a2[2 * j]     = pack_bf16(e0, e1);
                a2[2 * j + 1] = pack_bf16(e2, e3);
            }

            // ---- GEMM2: acc2[sel-n, l] += E . img; B = movmatrix(bsave) ----
            #pragma unroll
            for (int lb = 0; lb < 8; lb++) {
                uint32_t m0r = movm(bsave[lb][0]);
                uint32_t m1r = movm(bsave[lb][1]);
                uint32_t m2r = movm(bsave[lb][2]);
                uint32_t m3r = movm(bsave[lb][3]);
                mma_bf16(acc2[2 * lb],     a2, m0r, m2r);
                mma_bf16(acc2[2 * lb + 1], a2, m1r, m3r);
            }
        }
        __syncthreads();   // done reading IMGB before next convert
    }

    // store partials: g_part[bid][sel-n][l]
    int nbase = w * 16 + (lane >> 2);
    #pragma unroll
    for (int lt = 0; lt < 16; lt++) {
        int l = lt * 8 + 2 * (lane & 3);
        size_t base = (size_t)bid * 16384 + (size_t)nbase * 128 + l;
        *(float2*)&g_part[base] = make_float2(acc2[lt][0], acc2[lt][1]);
        *(float2*)&g_part[base + 8 * 128] = make_float2(acc2[lt][2], acc2[lt][3]);
    }
}

// ================= K2: split-K reduce partials + interp -> t_line =============
// 128 blocks x 128 thr. out-idx = B*16 + (t&15) in [0,2048) float4 units:
// w = out>>5, l4 = out&31. split = t>>4 handles 16 stripes.
__global__ void k_redtl() {
    __shared__ float4 red[128];
    int t = threadIdx.x, B = blockIdx.x;
    int out = B * 16 + (t & 15);
    int split = t >> 4;
    int w = out >> 5, l4 = out & 31;
    const float4* p4 = (const float4*)g_part;
    float4 s = make_float4(0.f, 0.f, 0.f, 0.f);
    #pragma unroll 4
    for (int st = split * 16; st < split * 16 + 16; st++) {
        float4 a = p4[(size_t)st * 4096 + (2 * w) * 32 + l4];
        float4 b = p4[(size_t)st * 4096 + (2 * w + 1) * 32 + l4];
        s.x += a.x + b.x; s.y += a.y + b.y;
        s.z += a.z + b.z; s.w += a.w + b.w;
    }
    red[t] = s;
    __syncthreads();
    if (t < 16) {
        float4 s2 = red[t];
        #pragma unroll
        for (int q = 1; q < 8; q++) {
            float4 r = red[t + 16 * q];
            s2.x += r.x; s2.y += r.y; s2.z += r.z; s2.w += r.w;
        }
        int o2 = B * 16 + t;
        int w2 = o2 >> 5, l42 = o2 & 31;
        g_tline[(4 * l42 + 0) * 64 + w2] = 0.5f * s2.x;
        g_tline[(4 * l42 + 1) * 64 + w2] = 0.5f * s2.y;
        g_tline[(4 * l42 + 2) * 64 + w2] = 0.5f * s2.z;
        g_tline[(4 * l42 + 3) * 64 + w2] = 0.5f * s2.w;
    }
}

// ================= K3: pre1 = b1 + W1a @ t_line =================
__global__ void k_pre1(const float* __restrict__ w1, const float* __restrict__ b1) {
    int f = blockIdx.x * 256 + threadIdx.x;   // f = b*4096 + o*64 + w
    int b = f >> 12, o = (f >> 6) & 63, w = f & 63;
    float s = __ldg(&b1[o]);
    #pragma unroll 8
    for (int c = 0; c < 64; c++)
        s = fmaf(__ldg(&w1[o * 128 + c]), g_tline[(b * 64 + c) * 64 + w], s);
    g_pre1[f] = s;
}

// ================= K4: per-voxel MLP + gated blend (fp16 mma) =================
// 1024 blocks x 512 thr; 256 voxels/block (two sequential 128-vox tiles).
// Epilogue: gate staged to smem (GT, reusing X16/H16 region) then a coalesced
// per-row blend pass (LDG.128/STG.128).
// smem: X16@0 (17408) | H16@17408 | GT@0 (64x528=33792, after X/H dead) |
//       W1@34816 (9216) | W2@44032 (9216) | PRE@53248 (17408) | TL@70656 |
//       total 88064
#define SVB 272
#define SWB 144
__global__ __launch_bounds__(512, 2) void k_mlp(const float* __restrict__ img,
                                                const float* __restrict__ w1,
                                                const float* __restrict__ w2,
                                                const float* __restrict__ b2,
                                                float* __restrict__ out) {
    extern __shared__ char dsm[];
    const int X16 = 0, H16 = 17408, GT = 0, W1O = 34816, W2O = 44032,
              PRE = 53248, TL = 70656;
    uint32_t sb = smem_u32(dsm);

    int t = threadIdx.x;
    int bb = blockIdx.x >> 9;
    int m0 = (blockIdx.x & 511) << 8;
    int w = t >> 5, lane = t & 31;
    int obase = (w & 3) * 16;
    int vwbase = (w >> 2) * 32;

    // ---- stage weights (fp16), pre1, tline (fp32) once per block ----
    for (int f = t; f < 2048; f += 512) {
        int o = f >> 5, c2 = f & 31;
        float2 a = *(const float2*)&w1[o * 128 + 64 + 2 * c2];
        *(uint32_t*)(dsm + W1O + o * SWB + c2 * 4) = pack_f16(a.x, a.y);
        float2 b = *(const float2*)&w2[o * 64 + 2 * c2];
        *(uint32_t*)(dsm + W2O + o * SWB + c2 * 4) = pack_f16(b.x, b.y);
    }
    for (int f = t; f < 1024; f += 512) {
        int o = f >> 4, w4 = f & 15;
        *(float4*)(dsm + PRE + o * 272 + w4 * 16) =
            *(const float4*)&g_pre1[bb * 4096 + o * 64 + w4 * 4];
        *(float4*)(dsm + TL + o * 272 + w4 * 16) =
            *(const float4*)&g_tline[bb * 4096 + o * 64 + w4 * 4];
    }

    int orow = obase + (lane >> 2);
    int vcol = 2 * (lane & 3);
    float bv0 = __ldg(&b2[orow]), bv1 = __ldg(&b2[orow + 8]);

    uint32_t aw_addr = (uint32_t)(obase + (lane & 15)) * SWB + (uint32_t)((lane >> 4) * 16);
    uint32_t bx_row = (uint32_t)(lane & 15) * SVB;
    uint32_t bx_col = (uint32_t)(vwbase * 2 + (lane >> 4) * 16);

    #pragma unroll 1
    for (int tile = 0; tile < 2; tile++) {
        int m0t = m0 + tile * 128;

        // ---- load x tile -> fp16 smem (wide) ----
        for (int f = t; f < 1024; f += 512) {
            int cc = f >> 3, v8 = f & 7;
            const float4* gp = (const float4*)(img + (size_t)(bb * 64 + cc) * M_DIM + m0t)
                             + v8 * 4;
            float4 x0 = gp[0], x1 = gp[1], x2 = gp[2], x3 = gp[3];
            *(uint4*)(dsm + X16 + cc * SVB + v8 * 32) =
                make_uint4(pack_f16(x0.x, x0.y), pack_f16(x0.z, x0.w),
                           pack_f16(x1.x, x1.y), pack_f16(x1.z, x1.w));
            *(uint4*)(dsm + X16 + cc * SVB + v8 * 32 + 16) =
                make_uint4(pack_f16(x2.x, x2.y), pack_f16(x2.z, x2.w),
                           pack_f16(x3.x, x3.y), pack_f16(x3.z, x3.w));
        }
        __syncthreads();   // X ready

        // ---- acc init from PRE smem ----
        float acc[4][4];
        #pragma unroll
        for (int j = 0; j < 4; j++) {
            int ws = (vwbase + 8 * j + vcol) & 63;
            float2 p0 = *(const float2*)(dsm + PRE + orow * 272 + ws * 4);
            float2 p1 = *(const float2*)(dsm + PRE + (orow + 8) * 272 + ws * 4);
            acc[j][0] = p0.x; acc[j][1] = p0.y;
            acc[j][2] = p1.x; acc[j][3] = p1.y;
        }

        // ---- layer 1: h = pre1 + W1b @ x ----
        #pragma unroll
        for (int k = 0; k < 4; k++) {
            uint32_t a[4];
            ldsm4(a, sb + W1O + aw_addr + k * 32u);
            #pragma unroll
            for (int q = 0; q < 2; q++) {
                uint32_t bx[4];
                ldsm4t(bx, sb + X16 + bx_row + (uint32_t)(16 * k) * SVB + bx_col + q * 32u);
                mma_f16(acc[2 * q],     a, bx[0], bx[1]);
                mma_f16(acc[2 * q + 1], a, bx[2], bx[3]);
            }
        }

        // ---- relu -> fp16 H smem ----
        #pragma unroll
        for (int j = 0; j < 4; j++) {
            int vox0 = vwbase + 8 * j + vcol;
            *(uint32_t*)(dsm + H16 + orow * SVB + vox0 * 2) =
                pack_f16(fmaxf(acc[j][0], 0.f), fmaxf(acc[j][1], 0.f));
            *(uint32_t*)(dsm + H16 + (orow + 8) * SVB + vox0 * 2) =
                pack_f16(fmaxf(acc[j][2], 0.f), fmaxf(acc[j][3], 0.f));
        }
        __syncthreads();

        // ---- layer 2: g = b2 + W2 @ H ----
        #pragma unroll
        for (int j = 0; j < 4; j++) {
            acc[j][0] = bv0; acc[j][1] = bv0;
            acc[j][2] = bv1; acc[j][3] = bv1;
        }
        #pragma unroll
        for (int k = 0; k < 4; k++) {
            uint32_t a[4];
            ldsm4(a, sb + W2O + aw_addr + k * 32u);
            #pragma unroll
            for (int q = 0; q < 2; q++) {
                uint32_t bh[4];
                ldsm4t(bh, sb + H16 + bx_row + (uint32_t)(16 * k) * SVB + bx_col + q * 32u);
                mma_f16(acc[2 * q],     a, bh[0], bh[1]);
                mma_f16(acc[2 * q + 1], a, bh[2], bh[3]);
            }
        }
        __syncthreads();   // all H reads done before GT overwrites that region

        // ---- gates -> smem GT [o][vox] fp32, pitch 528 ----
        #pragma unroll
        for (int j = 0; j < 4; j++) {
            int vox0 = vwbase + 8 * j + vcol;
            *(float2*)(dsm + GT + orow * 528 + vox0 * 4) =
                make_float2(mufu_sigmoid(acc[j][0]), mufu_sigmoid(acc[j][1]));
            *(float2*)(dsm + GT + (orow + 8) * 528 + vox0 * 4) =
                make_float2(mufu_sigmoid(acc[j][2]), mufu_sigmoid(acc[j][3]));
        }
        __syncthreads();

        // ---- coalesced blend pass: warp w owns rows 4w..4w+3 ----
        #pragma unroll
        for (int jr = 0; jr < 4; jr++) {
            int row = w * 4 + jr;
            size_t gidx = (size_t)(bb * 64 + row) * M_DIM + m0t + lane * 4;
            float4 xv = *(const float4*)(img + gidx);
            float4 gv = *(const float4*)(dsm + GT + row * 528 + lane * 16);
            float4 tv = *(const float4*)(dsm + TL + row * 272 + (lane & 15) * 16);
            float4 ov;
            ov.x = fmaf(gv.x, tv.x - xv.x, xv.x);
            ov.y = fmaf(gv.y, tv.y - xv.y, xv.y);
            ov.z = fmaf(gv.z, tv.z - xv.z, xv.z);
            ov.w = fmaf(gv.w, tv.w - xv.w, xv.w);
            *(float4*)(out + gidx) = ov;
        }
        __syncthreads();   // GT reads done before next tile's X load reuses region
    }
}

// ================= launch =================
extern "C" void kernel_launch(void* const* d_in, const int* in_sizes, int n_in,
                              void* d_out, int out_size) {
    const float* text = (const float*)d_in[0];
    const float* img  = (const float*)d_in[1];
    const float* w1   = (const float*)d_in[2];
    const float* b1   = (const float*)d_in[3];
    const float* w2   = (const float*)d_in[4];
    const float* b2   = (const float*)d_in[5];
    float* out = (float*)d_out;

    cudaFuncSetAttribute(k_fused, cudaFuncAttributeMaxDynamicSharedMemorySize, 209920);
    cudaFuncSetAttribute(k_mlp,   cudaFuncAttributeMaxDynamicSharedMemorySize, 88064);

    k_fused<<<128, 256, 209920>>>(img, text);
    k_redtl<<<128, 128>>>();
    k_pre1 <<<32, 256>>>(w1, b1);
    k_mlp  <<<1024, 512, 88064>>>(img, w1, w2, b2, out);
}